// round 2
// baseline (speedup 1.0000x reference)
#include <cuda_runtime.h>

// Problem constants (K=8192, L=128, D=64)
#define NTH   256
#define ROWS  64
#define NBLK  128          // 8192 / 64
#define LT    128
#define WS    258          // W_hh^T smem row stride (even, padded)
#define HS    68           // h smem row stride (multiple of 4, padded)

#define SMEM_FLOATS (64*WS + 2*64*HS + ROWS*LT + 256 + 256 + 1024)
#define SMEM_BYTES  (SMEM_FLOATS * 4)

// Deterministic per-block partials (no float atomics)
__device__ float g_Pfc[NBLK * 64];
__device__ float g_Phs[NBLK * 64];

__device__ __forceinline__ unsigned long long pk2(float lo, float hi) {
    unsigned long long r;
    asm("mov.b64 %0, {%1, %2};" : "=l"(r) : "f"(lo), "f"(hi));
    return r;
}
__device__ __forceinline__ void upk2(unsigned long long v, float& lo, float& hi) {
    asm("mov.b64 {%0, %1}, %2;" : "=f"(lo), "=f"(hi) : "l"(v));
}
// Packed dual-FMA (sm_100+): d = a*b + d on two packed fp32 lanes
#define FFMA2(d, a, b) asm("fma.rn.f32x2 %0, %1, %2, %0;" : "+l"(d) : "l"(a), "l"(b))

__device__ __forceinline__ float sigf(float x) {
    return 1.0f / (1.0f + __expf(-x));
}
__device__ __forceinline__ float tanh_f(float x) {
    float e = __expf(2.0f * x);
    return 1.0f - 2.0f / (e + 1.0f);
}

__global__ __launch_bounds__(NTH, 1)
void lstm_main(const float* __restrict__ x,
               const float* __restrict__ W_num, const float* __restrict__ b_num,
               const float* __restrict__ W_ih,  const float* __restrict__ W_hh,
               const float* __restrict__ b_ih,  const float* __restrict__ b_hh,
               const float* __restrict__ W_aout, const float* __restrict__ b_aout,
               const float* __restrict__ W_fh,   const float* __restrict__ b_fh)
{
    extern __shared__ float sm[];
    float* w_s  = sm;                      // [64][WS]  W_hh^T : w_s[j*WS+g] = W_hh[g][j]
    float* h_s  = w_s  + 64 * WS;          // [2][64][HS] transposed h : h[j][r]
    float* xr_s = h_s  + 2 * 64 * HS;      // [ROWS][LT]
    float* v_s  = xr_s + ROWS * LT;        // [256]  W_ih_h @ W_num
    float* cb_s = v_s  + 256;              // [256]  W_ih_h @ b_num + b_ih + b_hh
    float* red_s= cb_s + 256;              // [1024] reduction scratch

    const int tid = threadIdx.x;
    const int tr  = tid >> 5;              // warp id 0..7 -> row group
    const int tu  = tid & 31;              // lane -> unit pair 2*tu, 2*tu+1
    const int r0  = tr * 8;                // local rows r0..r0+7
    const int row_base = blockIdx.x * ROWS;

    // ---- stage W_hh^T ----
    for (int idx = tid; idx < 256 * 64; idx += NTH) {
        int g = idx >> 6, j = idx & 63;
        w_s[j * WS + g] = W_hh[idx];
    }
    // ---- stage this block's x rows ----
    for (int idx = tid; idx < ROWS * LT; idx += NTH)
        xr_s[idx] = x[row_base * LT + idx];
    // ---- zero h buffers ----
    for (int idx = tid; idx < 2 * 64 * HS; idx += NTH)
        h_s[idx] = 0.0f;
    // ---- rank-1 input precompute: v[g] = W_ih[:, :64][g]·W_num ; cb = bias-folded ----
    {
        int g = tid;  // exactly 256 gates
        const float* wr = W_ih + g * 128;   // W_ih is (256, 128); first 64 cols used
        float v = 0.0f, cb = 0.0f;
        #pragma unroll 8
        for (int j = 0; j < 64; ++j) {
            float w = wr[j];
            v  = fmaf(w, W_num[j], v);
            cb = fmaf(w, b_num[j], cb);
        }
        v_s[g]  = v;
        cb_s[g] = cb + b_ih[g] + b_hh[g];
    }
    __syncthreads();

    // cell state in registers: c_st[p][e][s] -> row r0+2p+e, unit 2*tu+s
    float c_st[4][2][2];
    #pragma unroll
    for (int p = 0; p < 4; ++p)
        #pragma unroll
        for (int e = 0; e < 2; ++e) { c_st[p][e][0] = 0.0f; c_st[p][e][1] = 0.0f; }

    // ================= recurrence: 128 sequential steps =================
    for (int t = 0; t < LT; ++t) {
        const float* hc = h_s + ((t    ) & 1) * (64 * HS);
        float*       hn = h_s + ((t + 1) & 1) * (64 * HS);

        float xv[8];
        #pragma unroll
        for (int i = 0; i < 8; ++i) xv[i] = xr_s[(r0 + i) * LT + t];

        // init gates with rank-1 input term + fused bias
        // acc[q][s][p] packs rows (r0+2p, r0+2p+1) for gate col q*64 + 2*tu + s
        unsigned long long acc[4][2][4];
        #pragma unroll
        for (int q = 0; q < 4; ++q)
            #pragma unroll
            for (int s = 0; s < 2; ++s) {
                int col = q * 64 + 2 * tu + s;
                float v = v_s[col], cb = cb_s[col];
                #pragma unroll
                for (int p = 0; p < 4; ++p)
                    acc[q][s][p] = pk2(fmaf(xv[2 * p], v, cb),
                                       fmaf(xv[2 * p + 1], v, cb));
            }

        // gates += h @ W_hh^T  (64-deep dots, packed dual FMA over row pairs)
        #pragma unroll 4
        for (int j = 0; j < 64; ++j) {
            const float* hj = hc + j * HS + r0;
            unsigned long long h2[4];
            #pragma unroll
            for (int p = 0; p < 4; ++p)
                h2[p] = *(const unsigned long long*)(hj + 2 * p);
            const float* wj = w_s + j * WS + 2 * tu;
            #pragma unroll
            for (int q = 0; q < 4; ++q) {
                float2 w = *(const float2*)(wj + q * 64);
                unsigned long long w0 = pk2(w.x, w.x);
                unsigned long long w1 = pk2(w.y, w.y);
                #pragma unroll
                for (int p = 0; p < 4; ++p) {
                    FFMA2(acc[q][0][p], h2[p], w0);
                    FFMA2(acc[q][1][p], h2[p], w1);
                }
            }
        }

        // activations + state update (gate order: i, f, g, o)
        #pragma unroll
        for (int p = 0; p < 4; ++p) {
            #pragma unroll
            for (int s = 0; s < 2; ++s) {
                float iA, iB, fA, fB, gA, gB, oA, oB;
                upk2(acc[0][s][p], iA, iB);
                upk2(acc[1][s][p], fA, fB);
                upk2(acc[2][s][p], gA, gB);
                upk2(acc[3][s][p], oA, oB);
                float cA = c_st[p][0][s], cB = c_st[p][1][s];
                cA = sigf(fA) * cA + sigf(iA) * tanh_f(gA);
                cB = sigf(fB) * cB + sigf(iB) * tanh_f(gB);
                c_st[p][0][s] = cA; c_st[p][1][s] = cB;
                float hA = sigf(oA) * tanh_f(cA);
                float hB = sigf(oB) * tanh_f(cB);
                int u = 2 * tu + s;
                hn[u * HS + r0 + 2 * p]     = hA;
                hn[u * HS + r0 + 2 * p + 1] = hB;
            }
        }
        __syncthreads();
    }

    // ================= tail: h_hat, f, block partial sums =================
    // final h is in buffer 0 (t=127 wrote (127+1)&1 = 0)
    const float* hf  = h_s;               // [j*HS + r]
    float* hh_s      = h_s + 64 * HS;     // reuse buffer 1 for h_hat^T
    float* wa_s      = w_s;               // [j*HS + u] W_aout^T
    float* wf_s      = w_s + 64 * HS;     // [j*HS + u] W_fh^T

    for (int idx = tid; idx < 4096; idx += NTH) {
        int u = idx >> 6, j = idx & 63;
        wa_s[j * HS + u] = W_aout[idx];
        wf_s[j * HS + u] = W_fh[idx];
    }
    __syncthreads();

    // h_hat = h @ W_aout^T + b_aout
    float hhat[4][2][2];
    {
        float b0 = b_aout[2 * tu], b1 = b_aout[2 * tu + 1];
        #pragma unroll
        for (int p = 0; p < 4; ++p)
            #pragma unroll
            for (int e = 0; e < 2; ++e) { hhat[p][e][0] = b0; hhat[p][e][1] = b1; }
        #pragma unroll 4
        for (int j = 0; j < 64; ++j) {
            const float* hj = hf + j * HS + r0;
            float wa0 = wa_s[j * HS + 2 * tu];
            float wa1 = wa_s[j * HS + 2 * tu + 1];
            #pragma unroll
            for (int p = 0; p < 4; ++p)
                #pragma unroll
                for (int e = 0; e < 2; ++e) {
                    float h = hj[2 * p + e];
                    hhat[p][e][0] = fmaf(h, wa0, hhat[p][e][0]);
                    hhat[p][e][1] = fmaf(h, wa1, hhat[p][e][1]);
                }
        }
        #pragma unroll
        for (int p = 0; p < 4; ++p)
            #pragma unroll
            for (int e = 0; e < 2; ++e)
                #pragma unroll
                for (int s = 0; s < 2; ++s)
                    hh_s[(2 * tu + s) * HS + r0 + 2 * p + e] = hhat[p][e][s];
    }
    __syncthreads();

    // f = h_hat @ W_fh^T + b_fh ; then partials
    float ff[4][2][2];
    {
        float b0 = b_fh[2 * tu], b1 = b_fh[2 * tu + 1];
        #pragma unroll
        for (int p = 0; p < 4; ++p)
            #pragma unroll
            for (int e = 0; e < 2; ++e) { ff[p][e][0] = b0; ff[p][e][1] = b1; }
        #pragma unroll 4
        for (int j = 0; j < 64; ++j) {
            const float* hj = hh_s + j * HS + r0;
            float wf0 = wf_s[j * HS + 2 * tu];
            float wf1 = wf_s[j * HS + 2 * tu + 1];
            #pragma unroll
            for (int p = 0; p < 4; ++p)
                #pragma unroll
                for (int e = 0; e < 2; ++e) {
                    float h = hj[2 * p + e];
                    ff[p][e][0] = fmaf(h, wf0, ff[p][e][0]);
                    ff[p][e][1] = fmaf(h, wf1, ff[p][e][1]);
                }
        }
    }

    float fcl[2] = {0.0f, 0.0f}, hsl[2] = {0.0f, 0.0f};
    #pragma unroll
    for (int p = 0; p < 4; ++p)
        #pragma unroll
        for (int e = 0; e < 2; ++e)
            #pragma unroll
            for (int s = 0; s < 2; ++s) {
                fcl[s] += sigf(ff[p][e][s]) * c_st[p][e][s];
                hsl[s] += hhat[p][e][s];
            }
    red_s[tr * 64 + 2 * tu]           = fcl[0];
    red_s[tr * 64 + 2 * tu + 1]       = fcl[1];
    red_s[512 + tr * 64 + 2 * tu]     = hsl[0];
    red_s[512 + tr * 64 + 2 * tu + 1] = hsl[1];
    __syncthreads();

    if (tid < 64) {
        float a = 0.0f, b = 0.0f;
        #pragma unroll
        for (int w = 0; w < 8; ++w) {
            a += red_s[w * 64 + tid];
            b += red_s[512 + w * 64 + tid];
        }
        g_Pfc[blockIdx.x * 64 + tid] = a;
        g_Phs[blockIdx.x * 64 + tid] = b;
    }
}

// ================= finale: reduce partials + object-cell head =================
__global__ void lstm_final(const float* __restrict__ W_iouh, const float* __restrict__ b_iouh,
                           const float* __restrict__ W_oout, const float* __restrict__ b_oout,
                           float* __restrict__ out)
{
    __shared__ float hsb[64];
    __shared__ float hob[64];
    int u = threadIdx.x;  // 64 threads

    float fc = 0.0f, hs = 0.0f;
    #pragma unroll 8
    for (int b = 0; b < NBLK; ++b) {
        fc += g_Pfc[b * 64 + u];
        hs += g_Phs[b * 64 + u];
    }
    hsb[u] = hs;
    __syncthreads();

    float ig = b_iouh[u], og = b_iouh[64 + u], ug = b_iouh[128 + u];
    #pragma unroll 8
    for (int j = 0; j < 64; ++j) {
        float h = hsb[j];
        ig = fmaf(h, W_iouh[u * 64 + j],         ig);
        og = fmaf(h, W_iouh[(64 + u) * 64 + j],  og);
        ug = fmaf(h, W_iouh[(128 + u) * 64 + j], ug);
    }
    float c_obj = sigf(ig) * tanh_f(ug) + fc;
    float h_obj = sigf(og) * tanh_f(c_obj);
    hob[u] = h_obj;
    __syncthreads();

    float hh = b_oout[u];
    #pragma unroll 8
    for (int j = 0; j < 64; ++j)
        hh = fmaf(hob[j], W_oout[u * 64 + j], hh);

    out[u]      = hh;
    out[64 + u] = c_obj;
}

extern "C" void kernel_launch(void* const* d_in, const int* in_sizes, int n_in,
                              void* d_out, int out_size)
{
    const float* x      = (const float*)d_in[0];
    const float* W_num  = (const float*)d_in[1];
    const float* b_num  = (const float*)d_in[2];
    const float* W_ih   = (const float*)d_in[3];
    const float* W_hh   = (const float*)d_in[4];
    const float* b_ih   = (const float*)d_in[5];
    const float* b_hh   = (const float*)d_in[6];
    const float* W_aout = (const float*)d_in[7];
    const float* b_aout = (const float*)d_in[8];
    const float* W_fh   = (const float*)d_in[9];
    const float* b_fh   = (const float*)d_in[10];
    const float* W_iouh = (const float*)d_in[11];
    const float* b_iouh = (const float*)d_in[12];
    const float* W_oout = (const float*)d_in[13];
    const float* b_oout = (const float*)d_in[14];

    (void)in_sizes; (void)n_in; (void)out_size;

    cudaFuncSetAttribute(lstm_main, cudaFuncAttributeMaxDynamicSharedMemorySize, SMEM_BYTES);

    lstm_main<<<NBLK, NTH, SMEM_BYTES>>>(x, W_num, b_num, W_ih, W_hh, b_ih, b_hh,
                                         W_aout, b_aout, W_fh, b_fh);
    lstm_final<<<1, 64>>>(W_iouh, b_iouh, W_oout, b_oout, (float*)d_out);
}

// round 3
// speedup vs baseline: 1.2269x; 1.2269x over previous
#include <cuda_runtime.h>

// Problem constants: K=8192, L=128, D=64
#define NTH   512
#define ROWS  64
#define NBLK  128          // 8192 / 64
#define LT    128
#define WSP   257          // W_hh^T smem row stride (odd -> conflict-free staging)
#define HPS   33           // u64 row-pairs per unit row (32 pairs + 1 pad)

// smem floats: W(64*257) + hp(2*64*33 u64 = *2 floats) + x(64*128) + v(256)+cb(256)+red(1024)
#define SMEM_FLOATS (64*WSP + 2*64*HPS*2 + ROWS*LT + 256 + 256 + 1024)
#define SMEM_BYTES  (SMEM_FLOATS * 4)

typedef unsigned long long u64;

// Deterministic per-block partials (no float atomics)
__device__ float g_Pfc[NBLK * 64];
__device__ float g_Phs[NBLK * 64];

__device__ __forceinline__ u64 pk2(float lo, float hi) {
    u64 r;
    asm("mov.b64 %0, {%1, %2};" : "=l"(r) : "f"(lo), "f"(hi));
    return r;
}
__device__ __forceinline__ void upk2(u64 v, float& lo, float& hi) {
    asm("mov.b64 {%0, %1}, %2;" : "=f"(lo), "=f"(hi) : "l"(v));
}
// Packed dual fp32 FMA (sm_100+): d = a*b + d on both lanes
#define FFMA2(d, a, b) asm("fma.rn.f32x2 %0, %1, %2, %0;" : "+l"(d) : "l"(a), "l"(b))

__device__ __forceinline__ float sigf(float x) {
    return 1.0f / (1.0f + __expf(-x));
}
__device__ __forceinline__ float tanh_f(float x) {
    float e = __expf(2.0f * x);
    return 1.0f - 2.0f / (e + 1.0f);
}

__global__ __launch_bounds__(NTH, 1)
void lstm_main(const float* __restrict__ x,
               const float* __restrict__ W_num, const float* __restrict__ b_num,
               const float* __restrict__ W_ih,  const float* __restrict__ W_hh,
               const float* __restrict__ b_ih,  const float* __restrict__ b_hh,
               const float* __restrict__ W_aout, const float* __restrict__ b_aout,
               const float* __restrict__ W_fh,   const float* __restrict__ b_fh)
{
    extern __shared__ float sm[];
    float* w_s  = sm;                                   // [64][WSP]  w_s[j*WSP+g] = W_hh[g][j]
    u64*   hp   = (u64*)(sm + 64 * WSP);                // [2][64][HPS] row-pair-packed h: hp[j][rp]
    float* x_s  = sm + 64 * WSP + 2 * 64 * HPS * 2;     // [ROWS][LT]
    float* v_s  = x_s + ROWS * LT;                      // [256]
    float* cb_s = v_s + 256;                            // [256]
    float* red_s= cb_s + 256;                           // [1024]

    const int tid  = threadIdx.x;
    const int w    = tid >> 5;
    const int l    = tid & 31;
    const int rg   = w >> 1;            // row group 0..7 -> rows rg*8 .. rg*8+7
    const int uh   = w & 1;             // unit half
    const int base = rg * 8;
    const int u    = uh * 32 + l;       // this thread's unit 0..63
    const int rp0  = rg * 4;            // first row-pair index

    // ---- stage W_hh^T (conflict-free: odd stride) ----
    for (int idx = tid; idx < 256 * 64; idx += NTH) {
        int g = idx >> 6, j = idx & 63;
        w_s[j * WSP + g] = W_hh[idx];
    }
    // ---- stage this block's x rows ----
    for (int idx = tid; idx < ROWS * LT; idx += NTH)
        x_s[idx] = x[(size_t)blockIdx.x * (ROWS * LT) + idx];
    // ---- zero hp buffers ----
    for (int idx = tid; idx < 2 * 64 * HPS; idx += NTH)
        hp[idx] = 0ull;
    // ---- rank-1 input precompute ----
    if (tid < 256) {
        int g = tid;
        const float* wr = W_ih + g * 128;   // W_ih is (256,128); first 64 cols used
        float v = 0.0f, cb = 0.0f;
        #pragma unroll 8
        for (int j = 0; j < 64; ++j) {
            float ww = wr[j];
            v  = fmaf(ww, W_num[j], v);
            cb = fmaf(ww, b_num[j], cb);
        }
        v_s[g]  = v;
        cb_s[g] = cb + b_ih[g] + b_hh[g];
    }
    __syncthreads();

    // step-invariant per-lane gate constants (duplicated packed)
    u64 v2[4], cb2[4];
    #pragma unroll
    for (int q = 0; q < 4; ++q) {
        float vv = v_s[q * 64 + u];
        float cc = cb_s[q * 64 + u];
        v2[q]  = pk2(vv, vv);
        cb2[q] = pk2(cc, cc);
    }

    float c_st[8];
    #pragma unroll
    for (int i = 0; i < 8; ++i) c_st[i] = 0.0f;

    // ================= recurrence: 128 sequential steps =================
    for (int t = 0; t < LT; ++t) {
        const u64* hc = hp + ((t    ) & 1) * (64 * HPS);
        u64*       hn = hp + ((t + 1) & 1) * (64 * HPS);

        // rank-1 input term (row-pair packed x)
        u64 xv2[4];
        #pragma unroll
        for (int p = 0; p < 4; ++p)
            xv2[p] = pk2(x_s[(base + 2 * p) * LT + t],
                         x_s[(base + 2 * p + 1) * LT + t]);

        u64 acc[4][4];
        #pragma unroll
        for (int q = 0; q < 4; ++q)
            #pragma unroll
            for (int p = 0; p < 4; ++p) {
                acc[q][p] = cb2[q];
                FFMA2(acc[q][p], xv2[p], v2[q]);
            }

        // gates += h @ W_hh^T : 64-deep contraction over units j
        #pragma unroll 16
        for (int j = 0; j < 64; ++j) {
            const u64* hj = hc + j * HPS + rp0;
            u64 h0 = hj[0], h1 = hj[1], h2 = hj[2], h3 = hj[3];   // broadcast LDS.64
            const float* wj = w_s + j * WSP + u;
            #pragma unroll
            for (int q = 0; q < 4; ++q) {
                float wv = wj[q * 64];
                u64 wd = pk2(wv, wv);
                FFMA2(acc[q][0], h0, wd);
                FFMA2(acc[q][1], h1, wd);
                FFMA2(acc[q][2], h2, wd);
                FFMA2(acc[q][3], h3, wd);
            }
        }

        // activations + state update (gate order: i, f, g, o)
        #pragma unroll
        for (int p = 0; p < 4; ++p) {
            float iA, iB, fA, fB, gA, gB, oA, oB;
            upk2(acc[0][p], iA, iB);
            upk2(acc[1][p], fA, fB);
            upk2(acc[2][p], gA, gB);
            upk2(acc[3][p], oA, oB);
            float cA = sigf(fA) * c_st[2 * p]     + sigf(iA) * tanh_f(gA);
            float cB = sigf(fB) * c_st[2 * p + 1] + sigf(iB) * tanh_f(gB);
            c_st[2 * p]     = cA;
            c_st[2 * p + 1] = cB;
            float hA = sigf(oA) * tanh_f(cA);
            float hB = sigf(oB) * tanh_f(cB);
            hn[u * HPS + rp0 + p] = pk2(hA, hB);
        }
        __syncthreads();
    }

    // ================= tail: h_hat, f, block partial sums =================
    const u64* hf = hp;                 // final h (t=127 wrote buffer 0)
    u64*       hh = hp + 64 * HPS;      // buffer 1 for h_hat pairs
    float* wa_s = w_s;                  // [j*65 + u] W_aout^T
    float* wf_s = w_s + 64 * 65;        // [j*65 + u] W_fh^T

    for (int idx = tid; idx < 4096; idx += NTH) {
        int uu = idx >> 6, j = idx & 63;
        wa_s[j * 65 + uu] = W_aout[idx];
        wf_s[j * 65 + uu] = W_fh[idx];
    }
    __syncthreads();

    // h_hat = h @ W_aout^T + b_aout
    u64 ha[4];
    {
        float ba = b_aout[u];
        #pragma unroll
        for (int p = 0; p < 4; ++p) ha[p] = pk2(ba, ba);
        #pragma unroll 16
        for (int j = 0; j < 64; ++j) {
            const u64* hj = hf + j * HPS + rp0;
            u64 h0 = hj[0], h1 = hj[1], h2 = hj[2], h3 = hj[3];
            float wv = wa_s[j * 65 + u];
            u64 wd = pk2(wv, wv);
            FFMA2(ha[0], h0, wd);
            FFMA2(ha[1], h1, wd);
            FFMA2(ha[2], h2, wd);
            FFMA2(ha[3], h3, wd);
        }
        #pragma unroll
        for (int p = 0; p < 4; ++p)
            hh[u * HPS + rp0 + p] = ha[p];
    }
    __syncthreads();

    // f = h_hat @ W_fh^T + b_fh
    u64 fa[4];
    {
        float bf = b_fh[u];
        #pragma unroll
        for (int p = 0; p < 4; ++p) fa[p] = pk2(bf, bf);
        #pragma unroll 16
        for (int j = 0; j < 64; ++j) {
            const u64* hj = hh + j * HPS + rp0;
            u64 h0 = hj[0], h1 = hj[1], h2 = hj[2], h3 = hj[3];
            float wv = wf_s[j * 65 + u];
            u64 wd = pk2(wv, wv);
            FFMA2(fa[0], h0, wd);
            FFMA2(fa[1], h1, wd);
            FFMA2(fa[2], h2, wd);
            FFMA2(fa[3], h3, wd);
        }
    }

    float fc = 0.0f, hsum = 0.0f;
    #pragma unroll
    for (int p = 0; p < 4; ++p) {
        float hA, hB, fA, fB;
        upk2(ha[p], hA, hB);
        upk2(fa[p], fA, fB);
        fc   += sigf(fA) * c_st[2 * p] + sigf(fB) * c_st[2 * p + 1];
        hsum += hA + hB;
    }
    red_s[rg * 64 + u]       = fc;
    red_s[512 + rg * 64 + u] = hsum;
    __syncthreads();

    if (tid < 64) {
        float a = 0.0f, b = 0.0f;
        #pragma unroll
        for (int g = 0; g < 8; ++g) {
            a += red_s[g * 64 + tid];
            b += red_s[512 + g * 64 + tid];
        }
        g_Pfc[blockIdx.x * 64 + tid] = a;
        g_Phs[blockIdx.x * 64 + tid] = b;
    }
}

// ================= finale: reduce partials + object-cell head =================
__global__ void lstm_final(const float* __restrict__ W_iouh, const float* __restrict__ b_iouh,
                           const float* __restrict__ W_oout, const float* __restrict__ b_oout,
                           float* __restrict__ out)
{
    __shared__ float s_fc[4][64];
    __shared__ float s_hs[4][64];
    __shared__ float hsb[64];
    __shared__ float hob[64];

    int tid = threadIdx.x;      // 256 threads
    int q = tid >> 6, u = tid & 63;

    float fc = 0.0f, hs = 0.0f;
    #pragma unroll 8
    for (int b = q; b < NBLK; b += 4) {
        fc += g_Pfc[b * 64 + u];
        hs += g_Phs[b * 64 + u];
    }
    s_fc[q][u] = fc;
    s_hs[q][u] = hs;
    __syncthreads();

    float fct = 0.0f;
    if (tid < 64) {
        float hst = 0.0f;
        #pragma unroll
        for (int k = 0; k < 4; ++k) { fct += s_fc[k][tid]; hst += s_hs[k][tid]; }
        hsb[tid] = hst;
    }
    __syncthreads();

    if (tid < 64) {
        float ig = b_iouh[tid], og = b_iouh[64 + tid], ug = b_iouh[128 + tid];
        #pragma unroll 8
        for (int j = 0; j < 64; ++j) {
            float h = hsb[j];
            ig = fmaf(h, W_iouh[tid * 64 + j],         ig);
            og = fmaf(h, W_iouh[(64 + tid) * 64 + j],  og);
            ug = fmaf(h, W_iouh[(128 + tid) * 64 + j], ug);
        }
        float c_obj = sigf(ig) * tanh_f(ug) + fct;
        float h_obj = sigf(og) * tanh_f(c_obj);
        hob[tid] = h_obj;
        out[64 + tid] = c_obj;
    }
    __syncthreads();

    if (tid < 64) {
        float hh = b_oout[tid];
        #pragma unroll 8
        for (int j = 0; j < 64; ++j)
            hh = fmaf(hob[j], W_oout[tid * 64 + j], hh);
        out[tid] = hh;
    }
}

extern "C" void kernel_launch(void* const* d_in, const int* in_sizes, int n_in,
                              void* d_out, int out_size)
{
    const float* x      = (const float*)d_in[0];
    const float* W_num  = (const float*)d_in[1];
    const float* b_num  = (const float*)d_in[2];
    const float* W_ih   = (const float*)d_in[3];
    const float* W_hh   = (const float*)d_in[4];
    const float* b_ih   = (const float*)d_in[5];
    const float* b_hh   = (const float*)d_in[6];
    const float* W_aout = (const float*)d_in[7];
    const float* b_aout = (const float*)d_in[8];
    const float* W_fh   = (const float*)d_in[9];
    const float* b_fh   = (const float*)d_in[10];
    const float* W_iouh = (const float*)d_in[11];
    const float* b_iouh = (const float*)d_in[12];
    const float* W_oout = (const float*)d_in[13];
    const float* b_oout = (const float*)d_in[14];

    (void)in_sizes; (void)n_in; (void)out_size;

    cudaFuncSetAttribute(lstm_main, cudaFuncAttributeMaxDynamicSharedMemorySize, SMEM_BYTES);

    lstm_main<<<NBLK, NTH, SMEM_BYTES>>>(x, W_num, b_num, W_ih, W_hh, b_ih, b_hh,
                                         W_aout, b_aout, W_fh, b_fh);
    lstm_final<<<1, 256>>>(W_iouh, b_iouh, W_oout, b_oout, (float*)d_out);
}

// round 5
// speedup vs baseline: 2.0448x; 1.6666x over previous
#include <cuda_runtime.h>
#include <cuda_bf16.h>
#include <cstdint>

// Problem: K=8192 rows, L=128 steps, D=64
#define NTH  512
#define NBLK 128
#define LT   128

// ---- smem byte offsets ----
#define HB_OFF   0         // 2 bufs x (hi 9216 + lo 9216) = 36864
#define HB_BUF   18432
#define HB_LO    9216
#define HROW     144       // 72 bf16 per row (conflict-free ldmatrix stride)
#define X_OFF    36864     // 64 x 132 f32 = 33792
#define XS       132
#define HF_OFF   70656     // final h [64][66] f32
#define CF_OFF   87552     // final c [64][66] f32
#define VS_OFF   104448    // v[256] reordered
#define CBS_OFF  105472    // cb[256] reordered
#define RED_OFF  106496    // 2 x 1024 f32
#define SMEM_BYTES 114688
// tail overlays (inside HB region, recurrence done)
#define WA_OFF   0
#define WF_OFF   16896

typedef unsigned long long u64;

__device__ float g_Pfc[NBLK * 64];
__device__ float g_Phs[NBLK * 64];

__device__ __forceinline__ uint32_t smem_u32(const void* p) {
    uint32_t a;
    asm("{ .reg .u64 t; cvta.to.shared.u64 t, %1; cvt.u32.u64 %0, t; }" : "=r"(a) : "l"(p));
    return a;
}
__device__ __forceinline__ void ldmx4(uint32_t* r, uint32_t addr) {
    asm volatile("ldmatrix.sync.aligned.m8n8.x4.shared.b16 {%0,%1,%2,%3}, [%4];"
                 : "=r"(r[0]), "=r"(r[1]), "=r"(r[2]), "=r"(r[3]) : "r"(addr));
}
__device__ __forceinline__ void mma16816(float* d, const uint32_t* a, const uint32_t* b) {
    asm volatile("mma.sync.aligned.m16n8k16.row.col.f32.bf16.bf16.f32 "
                 "{%0,%1,%2,%3}, {%4,%5,%6,%7}, {%8,%9}, {%0,%1,%2,%3};"
                 : "+f"(d[0]), "+f"(d[1]), "+f"(d[2]), "+f"(d[3])
                 : "r"(a[0]), "r"(a[1]), "r"(a[2]), "r"(a[3]), "r"(b[0]), "r"(b[1]));
}
__device__ __forceinline__ uint32_t pkbf2(float hi, float lo) {
    uint32_t r;
    asm("cvt.rn.bf16x2.f32 %0, %1, %2;" : "=r"(r) : "f"(hi), "f"(lo));
    return r;
}
__device__ __forceinline__ float bf_lo(uint32_t v) { return __uint_as_float(v << 16); }
__device__ __forceinline__ float bf_hi(uint32_t v) { return __uint_as_float(v & 0xFFFF0000u); }

__device__ __forceinline__ float sigf(float x)   { return 1.0f / (1.0f + __expf(-x)); }
__device__ __forceinline__ float tanh_f(float x) { float e = __expf(2.0f * x); return 1.0f - 2.0f / (e + 1.0f); }

__global__ __launch_bounds__(NTH, 1)
void lstm_main(const float* __restrict__ x,
               const float* __restrict__ W_num, const float* __restrict__ b_num,
               const float* __restrict__ W_ih,  const float* __restrict__ W_hh,
               const float* __restrict__ b_ih,  const float* __restrict__ b_hh,
               const float* __restrict__ W_aout, const float* __restrict__ b_aout,
               const float* __restrict__ W_fh,   const float* __restrict__ b_fh)
{
    extern __shared__ char smem[];
    const uint32_t sb = smem_u32(smem);

    float* x_s  = (float*)(smem + X_OFF);
    float* hf_s = (float*)(smem + HF_OFF);
    float* cf_s = (float*)(smem + CF_OFF);
    float* v_s  = (float*)(smem + VS_OFF);
    float* cb_s = (float*)(smem + CBS_OFF);
    float* red  = (float*)(smem + RED_OFF);

    const int tid  = threadIdx.x;
    const int l    = tid & 31;
    const int wid  = tid >> 5;
    const int wm   = wid >> 3;          // row-group: rows wm*32 .. +31
    const int wn   = wid & 7;           // gate-group: reordered gates wn*32 .. +31
    const int c    = l & 3;             // col-pair id
    const int quad = l >> 2;            // 0..7
    const int codd = c & 1;

    // ---- zero h buffer 0 (hi+lo) ----
    for (int i = tid; i < HB_BUF / 4; i += NTH) ((uint32_t*)(smem + HB_OFF))[i] = 0u;

    // ---- stage x rows (padded stride) ----
    {
        const float* xg = x + (size_t)blockIdx.x * (64 * LT);
        for (int i = tid; i < 64 * LT; i += NTH) x_s[(i >> 7) * XS + (i & 127)] = xg[i];
    }

    // ---- rank-1 input precompute, stored in reordered gate index m = 4u+q ----
    if (tid < 256) {
        int g = tid;                        // original gate index (q*64+u)
        const float* wr = W_ih + g * 128;   // (256,128); first 64 cols used
        float v = 0.0f, cb = 0.0f;
        #pragma unroll 8
        for (int j = 0; j < 64; ++j) {
            float ww = wr[j];
            v  = fmaf(ww, W_num[j], v);
            cb = fmaf(ww, b_num[j], cb);
        }
        int m = 4 * (g & 63) + (g >> 6);
        v_s[m]  = v;
        cb_s[m] = cb + b_ih[g] + b_hh[g];
    }

    // ---- B (weight) fragments, loop-invariant in registers ----
    // m16n8k16 row.col: frag b0 = {W[n][k0], W[n][k0+1]} (lo,hi), b1 = k0+8
    uint32_t Bh[4][4][2], Bl[4][4][2];
    #pragma unroll
    for (int nt = 0; nt < 4; ++nt) {
        int m = wn * 32 + nt * 8 + quad;        // reordered gate
        int g = (m & 3) * 64 + (m >> 2);        // original gate row in W_hh
        const float* wr = W_hh + g * 64;
        #pragma unroll
        for (int kk = 0; kk < 4; ++kk) {
            int j0 = kk * 16 + 2 * c;
            #pragma unroll
            for (int hb = 0; hb < 2; ++hb) {
                float w0 = wr[j0 + 8 * hb];
                float w1 = wr[j0 + 8 * hb + 1];
                uint32_t hi = pkbf2(w1, w0);
                float r0 = w0 - bf_lo(hi);
                float r1 = w1 - bf_hi(hi);
                Bh[nt][kk][hb] = hi;
                Bl[nt][kk][hb] = pkbf2(r1, r0);
            }
        }
    }
    __syncthreads();

    // per-thread step-invariant constants
    float vv[4][2], cc[4][2];
    #pragma unroll
    for (int nt = 0; nt < 4; ++nt)
        #pragma unroll
        for (int s = 0; s < 2; ++s) {
            int m = wn * 32 + nt * 8 + 2 * c + s;
            vv[nt][s] = v_s[m];
            cc[nt][s] = cb_s[m];
        }

    int rowA[2], rcell[2];
    #pragma unroll
    for (int mt = 0; mt < 2; ++mt) {
        rowA[mt]  = wm * 32 + mt * 16 + quad;
        rcell[mt] = rowA[mt] + (codd ? 8 : 0);
    }
    int Un[4];
    #pragma unroll
    for (int nt = 0; nt < 4; ++nt) Un[nt] = wn * 8 + nt * 2 + (c >> 1);

    float cst[2][4];
    #pragma unroll
    for (int mt = 0; mt < 2; ++mt)
        #pragma unroll
        for (int nt = 0; nt < 4; ++nt) cst[mt][nt] = 0.0f;

    const uint32_t abase = sb + HB_OFF + (wm * 32 + (l & 15)) * HROW + (l >> 4) * 16;

    // ================= recurrence: 128 sequential steps =================
    for (int t = 0; t < LT; ++t) {
        // --- init D with rank-1 x-term + fused bias ---
        float D[2][4][4];
        #pragma unroll
        for (int mt = 0; mt < 2; ++mt) {
            float xa = x_s[rowA[mt] * XS + t];
            float xb = x_s[(rowA[mt] + 8) * XS + t];
            #pragma unroll
            for (int nt = 0; nt < 4; ++nt) {
                D[mt][nt][0] = fmaf(xa, vv[nt][0], cc[nt][0]);
                D[mt][nt][1] = fmaf(xa, vv[nt][1], cc[nt][1]);
                D[mt][nt][2] = fmaf(xb, vv[nt][0], cc[nt][0]);
                D[mt][nt][3] = fmaf(xb, vv[nt][1], cc[nt][1]);
            }
        }

        // --- D += h @ W^T via bf16 mma with 3-way split ---
        const uint32_t ab = abase + (t & 1) * HB_BUF;
        #pragma unroll
        for (int kk = 0; kk < 4; ++kk) {
            uint32_t Ah[2][4], Al[2][4];
            #pragma unroll
            for (int mt = 0; mt < 2; ++mt) {
                ldmx4(Ah[mt], ab + mt * 16 * HROW + kk * 32);
                ldmx4(Al[mt], ab + HB_LO + mt * 16 * HROW + kk * 32);
            }
            #pragma unroll
            for (int mt = 0; mt < 2; ++mt)
                #pragma unroll
                for (int nt = 0; nt < 4; ++nt) {
                    mma16816(D[mt][nt], Ah[mt], Bh[nt][kk]);
                    mma16816(D[mt][nt], Al[mt], Bh[nt][kk]);
                    mma16816(D[mt][nt], Ah[mt], Bl[nt][kk]);
                }
        }

        // --- epilogue: pair-exchange, activations, write h ---
        char* hnext = smem + HB_OFF + ((t + 1) & 1) * HB_BUF;
        #pragma unroll
        for (int mt = 0; mt < 2; ++mt)
            #pragma unroll
            for (int nt = 0; nt < 4; ++nt) {
                float* d = D[mt][nt];
                float s0 = codd ? d[0] : d[2];
                float s1 = codd ? d[1] : d[3];
                float r0 = __shfl_xor_sync(0xFFFFFFFFu, s0, 1);
                float r1 = __shfl_xor_sync(0xFFFFFFFFu, s1, 1);
                float gi = codd ? r0 : d[0];
                float gf = codd ? r1 : d[1];
                float gg = codd ? d[2] : r0;
                float go = codd ? d[3] : r1;

                float cn = sigf(gf) * cst[mt][nt] + sigf(gi) * tanh_f(gg);
                cst[mt][nt] = cn;
                float hv = sigf(go) * tanh_f(cn);

                int r = rcell[mt];
                int U = Un[nt];
                if (t < LT - 1) {
                    __nv_bfloat16 hh = __float2bfloat16(hv);
                    float hl = hv - __bfloat162float(hh);
                    *(__nv_bfloat16*)(hnext + r * HROW + 2 * U) = hh;
                    *(__nv_bfloat16*)(hnext + HB_LO + r * HROW + 2 * U) = __float2bfloat16(hl);
                } else {
                    hf_s[r * 66 + U] = hv;
                    cf_s[r * 66 + U] = cn;
                }
            }
        __syncthreads();
    }

    // ================= tail =================
    float* wa = (float*)(smem + WA_OFF);   // [j*66+u]
    float* wf = (float*)(smem + WF_OFF);
    for (int idx = tid; idx < 4096; idx += NTH) {
        int u = idx >> 6, j = idx & 63;
        wa[j * 66 + u] = W_aout[idx];
        wf[j * 66 + u] = W_fh[idx];
    }
    __syncthreads();

    const int tw = wid;            // 16 warps
    const int r0 = tw * 4;         // rows r0..r0+3
    const int u0 = 2 * l;          // units u0, u0+1
    float* hs2 = x_s;              // reuse x region for h_hat [r][66]

    // h_hat = h @ W_aout^T + b_aout
    float hh2[2][4];
    {
        float b0 = b_aout[u0], b1 = b_aout[u0 + 1];
        #pragma unroll
        for (int rr = 0; rr < 4; ++rr) { hh2[0][rr] = b0; hh2[1][rr] = b1; }
        #pragma unroll 8
        for (int j = 0; j < 64; ++j) {
            float w0 = wa[j * 66 + u0], w1 = wa[j * 66 + u0 + 1];
            #pragma unroll
            for (int rr = 0; rr < 4; ++rr) {
                float hj = hf_s[(r0 + rr) * 66 + j];
                hh2[0][rr] = fmaf(hj, w0, hh2[0][rr]);
                hh2[1][rr] = fmaf(hj, w1, hh2[1][rr]);
            }
        }
        #pragma unroll
        for (int rr = 0; rr < 4; ++rr) {
            hs2[(r0 + rr) * 66 + u0]     = hh2[0][rr];
            hs2[(r0 + rr) * 66 + u0 + 1] = hh2[1][rr];
        }
    }
    __syncthreads();

    // f = h_hat @ W_fh^T + b_fh ; partial sums
    float fv2[2][4];
    {
        float b0 = b_fh[u0], b1 = b_fh[u0 + 1];
        #pragma unroll
        for (int rr = 0; rr < 4; ++rr) { fv2[0][rr] = b0; fv2[1][rr] = b1; }
        #pragma unroll 8
        for (int j = 0; j < 64; ++j) {
            float w0 = wf[j * 66 + u0], w1 = wf[j * 66 + u0 + 1];
            #pragma unroll
            for (int rr = 0; rr < 4; ++rr) {
                float hj = hs2[(r0 + rr) * 66 + j];
                fv2[0][rr] = fmaf(hj, w0, fv2[0][rr]);
                fv2[1][rr] = fmaf(hj, w1, fv2[1][rr]);
            }
        }
    }

    float fc0 = 0.0f, fc1 = 0.0f, hs0 = 0.0f, hs1 = 0.0f;
    #pragma unroll
    for (int rr = 0; rr < 4; ++rr) {
        fc0 += sigf(fv2[0][rr]) * cf_s[(r0 + rr) * 66 + u0];
        fc1 += sigf(fv2[1][rr]) * cf_s[(r0 + rr) * 66 + u0 + 1];
        hs0 += hh2[0][rr];
        hs1 += hh2[1][rr];
    }
    red[tw * 64 + u0]            = fc0;
    red[tw * 64 + u0 + 1]        = fc1;
    red[1024 + tw * 64 + u0]     = hs0;
    red[1024 + tw * 64 + u0 + 1] = hs1;
    __syncthreads();

    if (tid < 64) {
        float a = 0.0f, b = 0.0f;
        #pragma unroll
        for (int g = 0; g < 16; ++g) {
            a += red[g * 64 + tid];
            b += red[1024 + g * 64 + tid];
        }
        g_Pfc[blockIdx.x * 64 + tid] = a;
        g_Phs[blockIdx.x * 64 + tid] = b;
    }
}

// ================= finale: reduce partials + object-cell head =================
__global__ void lstm_final(const float* __restrict__ W_iouh, const float* __restrict__ b_iouh,
                           const float* __restrict__ W_oout, const float* __restrict__ b_oout,
                           float* __restrict__ out)
{
    __shared__ float s_fc[4][64];
    __shared__ float s_hs[4][64];
    __shared__ float hsb[64];
    __shared__ float hob[64];

    int tid = threadIdx.x;      // 256 threads
    int q = tid >> 6, u = tid & 63;

    float fc = 0.0f, hs = 0.0f;
    #pragma unroll 8
    for (int b = q; b < NBLK; b += 4) {
        fc += g_Pfc[b * 64 + u];
        hs += g_Phs[b * 64 + u];
    }
    s_fc[q][u] = fc;
    s_hs[q][u] = hs;
    __syncthreads();

    float fct = 0.0f;
    if (tid < 64) {
        float hst = 0.0f;
        #pragma unroll
        for (int k = 0; k < 4; ++k) { fct += s_fc[k][tid]; hst += s_hs[k][tid]; }
        hsb[tid] = hst;
    }
    __syncthreads();

    if (tid < 64) {
        float ig = b_iouh[tid], og = b_iouh[64 + tid], ug = b_iouh[128 + tid];
        #pragma unroll 8
        for (int j = 0; j < 64; ++j) {
            float h = hsb[j];
            ig = fmaf(h, W_iouh[tid * 64 + j],         ig);
            og = fmaf(h, W_iouh[(64 + tid) * 64 + j],  og);
            ug = fmaf(h, W_iouh[(128 + tid) * 64 + j], ug);
        }
        float c_obj = sigf(ig) * tanh_f(ug) + fct;
        float h_obj = sigf(og) * tanh_f(c_obj);
        hob[tid] = h_obj;
        out[64 + tid] = c_obj;
    }
    __syncthreads();

    if (tid < 64) {
        float hh = b_oout[tid];
        #pragma unroll 8
        for (int j = 0; j < 64; ++j)
            hh = fmaf(hob[j], W_oout[tid * 64 + j], hh);
        out[tid] = hh;
    }
}

extern "C" void kernel_launch(void* const* d_in, const int* in_sizes, int n_in,
                              void* d_out, int out_size)
{
    const float* x      = (const float*)d_in[0];
    const float* W_num  = (const float*)d_in[1];
    const float* b_num  = (const float*)d_in[2];
    const float* W_ih   = (const float*)d_in[3];
    const float* W_hh   = (const float*)d_in[4];
    const float* b_ih   = (const float*)d_in[5];
    const float* b_hh   = (const float*)d_in[6];
    const float* W_aout = (const float*)d_in[7];
    const float* b_aout = (const float*)d_in[8];
    const float* W_fh   = (const float*)d_in[9];
    const float* b_fh   = (const float*)d_in[10];
    const float* W_iouh = (const float*)d_in[11];
    const float* b_iouh = (const float*)d_in[12];
    const float* W_oout = (const float*)d_in[13];
    const float* b_oout = (const float*)d_in[14];

    (void)in_sizes; (void)n_in; (void)out_size;

    cudaFuncSetAttribute(lstm_main, cudaFuncAttributeMaxDynamicSharedMemorySize, SMEM_BYTES);

    lstm_main<<<NBLK, NTH, SMEM_BYTES>>>(x, W_num, b_num, W_ih, W_hh, b_ih, b_hh,
                                         W_aout, b_aout, W_fh, b_fh);
    lstm_final<<<1, 256>>>(W_iouh, b_iouh, W_oout, b_oout, (float*)d_out);
}

// round 6
// speedup vs baseline: 2.4342x; 1.1904x over previous
#include <cuda_runtime.h>
#include <cuda_fp16.h>
#include <cstdint>

// Problem: K=8192 rows, L=128 steps, D=64
#define NTH  512
#define NBLK 128
#define LT   128

// ---- smem byte offsets ----
#define HROW    144        // 64 fp16 = 128B data + 16B pad per row
#define HB_OFF  0          // 2 x 64 x 144 = 18432
#define HB_BUF  9216
#define X_OFF   18432      // 64 x 132 f32 = 33792
#define XS      132
#define BL_OFF  52224      // W_lo frags: 8wn x 4kk x 4nt x 32l x 8B = 32768
#define HF_OFF  84992      // final h [64][66] f32 = 16896
#define CF_OFF  101888     // final c [64][66] f32 = 16896
#define VCB_OFF 118784     // float2[256] = 2048
#define RED_OFF 120832     // 2 x 1024 f32 = 8192
#define SMEM_BYTES 129024
// tail overlays (recurrence-only regions reused)
#define WA_OFF  0
#define WF_OFF  X_OFF
#define HS2_OFF BL_OFF

typedef unsigned long long u64;

__device__ float g_Pfc[NBLK * 64];
__device__ float g_Phs[NBLK * 64];

__device__ __forceinline__ uint32_t smem_u32(const void* p) {
    uint32_t a;
    asm("{ .reg .u64 t; cvta.to.shared.u64 t, %1; cvt.u32.u64 %0, t; }" : "=r"(a) : "l"(p));
    return a;
}
__device__ __forceinline__ void ldmx4(uint32_t* r, uint32_t addr) {
    asm volatile("ldmatrix.sync.aligned.m8n8.x4.shared.b16 {%0,%1,%2,%3}, [%4];"
                 : "=r"(r[0]), "=r"(r[1]), "=r"(r[2]), "=r"(r[3]) : "r"(addr));
}
__device__ __forceinline__ void mma16816(float* d, const uint32_t* a, const uint32_t* b) {
    asm volatile("mma.sync.aligned.m16n8k16.row.col.f32.f16.f16.f32 "
                 "{%0,%1,%2,%3}, {%4,%5,%6,%7}, {%8,%9}, {%0,%1,%2,%3};"
                 : "+f"(d[0]), "+f"(d[1]), "+f"(d[2]), "+f"(d[3])
                 : "r"(a[0]), "r"(a[1]), "r"(a[2]), "r"(a[3]), "r"(b[0]), "r"(b[1]));
}
__device__ __forceinline__ uint32_t pkh2(__half lo, __half hi) {
    return ((uint32_t)__half_as_ushort(hi) << 16) | __half_as_ushort(lo);
}
__device__ __forceinline__ float sigf(float x)   { return 1.0f / (1.0f + __expf(-x)); }
__device__ __forceinline__ float tanh_f(float x) { float e = __expf(2.0f * x); return 1.0f - 2.0f / (e + 1.0f); }

__global__ __launch_bounds__(NTH, 1)
void lstm_main(const float* __restrict__ x,
               const float* __restrict__ W_num, const float* __restrict__ b_num,
               const float* __restrict__ W_ih,  const float* __restrict__ W_hh,
               const float* __restrict__ b_ih,  const float* __restrict__ b_hh,
               const float* __restrict__ W_aout, const float* __restrict__ b_aout,
               const float* __restrict__ W_fh,   const float* __restrict__ b_fh)
{
    extern __shared__ char smem[];
    const uint32_t sb = smem_u32(smem);

    float*  x_s   = (float*)(smem + X_OFF);
    float*  hf_s  = (float*)(smem + HF_OFF);
    float*  cf_s  = (float*)(smem + CF_OFF);
    float2* vcb_s = (float2*)(smem + VCB_OFF);
    float*  red   = (float*)(smem + RED_OFF);

    const int tid  = threadIdx.x;
    const int l    = tid & 31;
    const int wid  = tid >> 5;
    const int wm   = wid >> 3;          // row-group: rows wm*32 .. +31
    const int wn   = wid & 7;           // unit-group: units wn*8 .. +7
    const int c    = l & 3;
    const int quad = l >> 2;
    const int u0   = 8 * wn + 2 * c;    // this thread's unit pair u0, u0+1

    // ---- zero h buffer 0 (h(0)=0) ----
    for (int i = tid; i < HB_BUF / 4; i += NTH) ((uint32_t*)(smem + HB_OFF))[i] = 0u;

    // ---- stage x rows (padded stride, bank-spread) ----
    {
        const float* xg = x + (size_t)blockIdx.x * (64 * LT);
        for (int i = tid; i < 64 * LT; i += NTH) x_s[(i >> 7) * XS + (i & 127)] = xg[i];
    }

    // ---- rank-1 input precompute, stored at remapped gate index m ----
    // orig gate g = q*64+u (q: 0=i,1=f,2=g,3=o)
    // m = (q>>1)*128 + (u>>3)*16 + (u&1)*8 + ((u>>1)&3)*2 + (q&1)
    if (tid < 256) {
        int g = tid;
        const float* wr = W_ih + g * 128;   // (256,128); first 64 cols used
        float v = 0.0f, cb = 0.0f;
        #pragma unroll 8
        for (int j = 0; j < 64; ++j) {
            float ww = wr[j];
            v  = fmaf(ww, W_num[j], v);
            cb = fmaf(ww, b_num[j], cb);
        }
        int q = g >> 6, u = g & 63;
        int m = (q >> 1) * 128 + (u >> 3) * 16 + (u & 1) * 8 + ((u >> 1) & 3) * 2 + (q & 1);
        vcb_s[m] = make_float2(v, cb + b_ih[g] + b_hh[g]);
    }

    // ---- W fragments: hi in regs, lo in smem ----
    // tile nt: col n=quad -> unit u = 8wn + 2*(quad>>1) + (nt&1), type q = (nt>>1)*2 + (quad&1)
    uint32_t Bh[4][4][2];
    #pragma unroll
    for (int nt = 0; nt < 4; ++nt) {
        int u = 8 * wn + 2 * (quad >> 1) + (nt & 1);
        int q = (nt >> 1) * 2 + (quad & 1);
        const float* wr = W_hh + (q * 64 + u) * 64;
        #pragma unroll
        for (int kk = 0; kk < 4; ++kk) {
            int j0 = kk * 16 + 2 * c;
            float w00 = wr[j0], w01 = wr[j0 + 1], w10 = wr[j0 + 8], w11 = wr[j0 + 9];
            __half a00 = __float2half(w00), a01 = __float2half(w01);
            __half a10 = __float2half(w10), a11 = __float2half(w11);
            Bh[nt][kk][0] = pkh2(a00, a01);
            Bh[nt][kk][1] = pkh2(a10, a11);
            if (wm == 0) {
                __half l00 = __float2half(w00 - __half2float(a00));
                __half l01 = __float2half(w01 - __half2float(a01));
                __half l10 = __float2half(w10 - __half2float(a10));
                __half l11 = __float2half(w11 - __half2float(a11));
                u64 v = ((u64)pkh2(l10, l11) << 32) | pkh2(l00, l01);
                *(u64*)(smem + BL_OFF + ((((wn * 4 + kk) * 4 + nt) * 32) + l) * 8) = v;
            }
        }
    }
    __syncthreads();

    float cst[2][2][2];   // [mt][rr][z]
    #pragma unroll
    for (int mt = 0; mt < 2; ++mt)
        #pragma unroll
        for (int rr = 0; rr < 2; ++rr) { cst[mt][rr][0] = 0.0f; cst[mt][rr][1] = 0.0f; }

    const uint32_t abase = sb + HB_OFF + (wm * 32 + (l & 15)) * HROW + (l >> 4) * 16;

    // ================= recurrence: 128 sequential steps =================
    for (int t = 0; t < LT; ++t) {
        // --- init D with rank-1 x-term + fused bias ---
        float D[2][4][4];
        float xv[2][2];
        #pragma unroll
        for (int mt = 0; mt < 2; ++mt) {
            int ra = wm * 32 + mt * 16 + quad;
            xv[mt][0] = x_s[ra * XS + t];
            xv[mt][1] = x_s[(ra + 8) * XS + t];
        }
        #pragma unroll
        for (int nt = 0; nt < 4; ++nt) {
            int mb = (nt >> 1) * 128 + wn * 16 + (nt & 1) * 8 + 2 * c;
            float2 p0 = vcb_s[mb], p1 = vcb_s[mb + 1];
            #pragma unroll
            for (int mt = 0; mt < 2; ++mt) {
                D[mt][nt][0] = fmaf(xv[mt][0], p0.x, p0.y);
                D[mt][nt][1] = fmaf(xv[mt][0], p1.x, p1.y);
                D[mt][nt][2] = fmaf(xv[mt][1], p0.x, p0.y);
                D[mt][nt][3] = fmaf(xv[mt][1], p1.x, p1.y);
            }
        }

        // --- D += h @ W^T : fp16 mma, W 2-way split (hi regs, lo smem) ---
        const uint32_t ab = abase + (t & 1) * HB_BUF;
        #pragma unroll
        for (int kk = 0; kk < 4; ++kk) {
            uint32_t Ah0[4], Ah1[4];
            ldmx4(Ah0, ab + kk * 32);
            ldmx4(Ah1, ab + 16 * HROW + kk * 32);
            #pragma unroll
            for (int nt = 0; nt < 4; ++nt) {
                u64 blv = *(const u64*)(smem + BL_OFF + ((((wn * 4 + kk) * 4 + nt) * 32) + l) * 8);
                uint32_t bl[2] = { (uint32_t)blv, (uint32_t)(blv >> 32) };
                mma16816(D[0][nt], Ah0, Bh[nt][kk]);
                mma16816(D[1][nt], Ah1, Bh[nt][kk]);
                mma16816(D[0][nt], Ah0, bl);
                mma16816(D[1][nt], Ah1, bl);
            }
        }

        // --- epilogue: activations, packed h store (no shfl) ---
        char* hnext = smem + HB_OFF + ((t + 1) & 1) * HB_BUF;
        #pragma unroll
        for (int mt = 0; mt < 2; ++mt)
            #pragma unroll
            for (int rr = 0; rr < 2; ++rr) {
                int row = wm * 32 + mt * 16 + quad + 8 * rr;
                float hz[2];
                #pragma unroll
                for (int z = 0; z < 2; ++z) {
                    float gi = D[mt][z][2 * rr];
                    float gf = D[mt][z][2 * rr + 1];
                    float gg = D[mt][2 + z][2 * rr];
                    float go = D[mt][2 + z][2 * rr + 1];
                    float cn = sigf(gf) * cst[mt][rr][z] + sigf(gi) * tanh_f(gg);
                    cst[mt][rr][z] = cn;
                    hz[z] = sigf(go) * tanh_f(cn);
                    if (t == LT - 1) {
                        hf_s[row * 66 + u0 + z] = hz[z];
                        cf_s[row * 66 + u0 + z] = cn;
                    }
                }
                if (t < LT - 1) {
                    __half2 hp = __floats2half2_rn(hz[0], hz[1]);
                    *(uint32_t*)(hnext + row * HROW + 2 * u0) = *(uint32_t*)&hp;
                }
            }
        __syncthreads();
    }

    // ================= tail =================
    float* wa  = (float*)(smem + WA_OFF);    // [j*66+u]
    float* wf  = (float*)(smem + WF_OFF);
    float* hs2 = (float*)(smem + HS2_OFF);   // h_hat staging [r][66]
    for (int idx = tid; idx < 4096; idx += NTH) {
        int u = idx >> 6, j = idx & 63;
        wa[j * 66 + u] = W_aout[idx];
        wf[j * 66 + u] = W_fh[idx];
    }
    __syncthreads();

    const int tw = wid;            // 16 warps
    const int r0 = tw * 4;         // rows r0..r0+3
    const int tu = 2 * l;          // units tu, tu+1

    // h_hat = h @ W_aout^T + b_aout
    float hh2[2][4];
    {
        float b0 = b_aout[tu], b1 = b_aout[tu + 1];
        #pragma unroll
        for (int rr = 0; rr < 4; ++rr) { hh2[0][rr] = b0; hh2[1][rr] = b1; }
        #pragma unroll 8
        for (int j = 0; j < 64; ++j) {
            float w0 = wa[j * 66 + tu], w1 = wa[j * 66 + tu + 1];
            #pragma unroll
            for (int rr = 0; rr < 4; ++rr) {
                float hj = hf_s[(r0 + rr) * 66 + j];
                hh2[0][rr] = fmaf(hj, w0, hh2[0][rr]);
                hh2[1][rr] = fmaf(hj, w1, hh2[1][rr]);
            }
        }
        #pragma unroll
        for (int rr = 0; rr < 4; ++rr) {
            hs2[(r0 + rr) * 66 + tu]     = hh2[0][rr];
            hs2[(r0 + rr) * 66 + tu + 1] = hh2[1][rr];
        }
    }
    __syncthreads();

    // f = h_hat @ W_fh^T + b_fh ; partial sums
    float fv2[2][4];
    {
        float b0 = b_fh[tu], b1 = b_fh[tu + 1];
        #pragma unroll
        for (int rr = 0; rr < 4; ++rr) { fv2[0][rr] = b0; fv2[1][rr] = b1; }
        #pragma unroll 8
        for (int j = 0; j < 64; ++j) {
            float w0 = wf[j * 66 + tu], w1 = wf[j * 66 + tu + 1];
            #pragma unroll
            for (int rr = 0; rr < 4; ++rr) {
                float hj = hs2[(r0 + rr) * 66 + j];
                fv2[0][rr] = fmaf(hj, w0, fv2[0][rr]);
                fv2[1][rr] = fmaf(hj, w1, fv2[1][rr]);
            }
        }
    }

    float fc0 = 0.0f, fc1 = 0.0f, hs0 = 0.0f, hs1 = 0.0f;
    #pragma unroll
    for (int rr = 0; rr < 4; ++rr) {
        fc0 += sigf(fv2[0][rr]) * cf_s[(r0 + rr) * 66 + tu];
        fc1 += sigf(fv2[1][rr]) * cf_s[(r0 + rr) * 66 + tu + 1];
        hs0 += hh2[0][rr];
        hs1 += hh2[1][rr];
    }
    red[tw * 64 + tu]            = fc0;
    red[tw * 64 + tu + 1]        = fc1;
    red[1024 + tw * 64 + tu]     = hs0;
    red[1024 + tw * 64 + tu + 1] = hs1;
    __syncthreads();

    if (tid < 64) {
        float a = 0.0f, b = 0.0f;
        #pragma unroll
        for (int g = 0; g < 16; ++g) {
            a += red[g * 64 + tid];
            b += red[1024 + g * 64 + tid];
        }
        g_Pfc[blockIdx.x * 64 + tid] = a;
        g_Phs[blockIdx.x * 64 + tid] = b;
    }
}

// ================= finale: reduce partials + object-cell head =================
__global__ void lstm_final(const float* __restrict__ W_iouh, const float* __restrict__ b_iouh,
                           const float* __restrict__ W_oout, const float* __restrict__ b_oout,
                           float* __restrict__ out)
{
    __shared__ float s_fc[4][64];
    __shared__ float s_hs[4][64];
    __shared__ float hsb[64];
    __shared__ float hob[64];

    int tid = threadIdx.x;      // 256 threads
    int q = tid >> 6, u = tid & 63;

    float fc = 0.0f, hs = 0.0f;
    #pragma unroll 8
    for (int b = q; b < NBLK; b += 4) {
        fc += g_Pfc[b * 64 + u];
        hs += g_Phs[b * 64 + u];
    }
    s_fc[q][u] = fc;
    s_hs[q][u] = hs;
    __syncthreads();

    float fct = 0.0f;
    if (tid < 64) {
        float hst = 0.0f;
        #pragma unroll
        for (int k = 0; k < 4; ++k) { fct += s_fc[k][tid]; hst += s_hs[k][tid]; }
        hsb[tid] = hst;
    }
    __syncthreads();

    if (tid < 64) {
        float ig = b_iouh[tid], og = b_iouh[64 + tid], ug = b_iouh[128 + tid];
        #pragma unroll 8
        for (int j = 0; j < 64; ++j) {
            float h = hsb[j];
            ig = fmaf(h, W_iouh[tid * 64 + j],         ig);
            og = fmaf(h, W_iouh[(64 + tid) * 64 + j],  og);
            ug = fmaf(h, W_iouh[(128 + tid) * 64 + j], ug);
        }
        float c_obj = sigf(ig) * tanh_f(ug) + fct;
        float h_obj = sigf(og) * tanh_f(c_obj);
        hob[tid] = h_obj;
        out[64 + tid] = c_obj;
    }
    __syncthreads();

    if (tid < 64) {
        float hh = b_oout[tid];
        #pragma unroll 8
        for (int j = 0; j < 64; ++j)
            hh = fmaf(hob[j], W_oout[tid * 64 + j], hh);
        out[tid] = hh;
    }
}

extern "C" void kernel_launch(void* const* d_in, const int* in_sizes, int n_in,
                              void* d_out, int out_size)
{
    const float* x      = (const float*)d_in[0];
    const float* W_num  = (const float*)d_in[1];
    const float* b_num  = (const float*)d_in[2];
    const float* W_ih   = (const float*)d_in[3];
    const float* W_hh   = (const float*)d_in[4];
    const float* b_ih   = (const float*)d_in[5];
    const float* b_hh   = (const float*)d_in[6];
    const float* W_aout = (const float*)d_in[7];
    const float* b_aout = (const float*)d_in[8];
    const float* W_fh   = (const float*)d_in[9];
    const float* b_fh   = (const float*)d_in[10];
    const float* W_iouh = (const float*)d_in[11];
    const float* b_iouh = (const float*)d_in[12];
    const float* W_oout = (const float*)d_in[13];
    const float* b_oout = (const float*)d_in[14];

    (void)in_sizes; (void)n_in; (void)out_size;

    cudaFuncSetAttribute(lstm_main, cudaFuncAttributeMaxDynamicSharedMemorySize, SMEM_BYTES);

    lstm_main<<<NBLK, NTH, SMEM_BYTES>>>(x, W_num, b_num, W_ih, W_hh, b_ih, b_hh,
                                         W_aout, b_aout, W_fh, b_fh);
    lstm_final<<<1, 256>>>(W_iouh, b_iouh, W_oout, b_oout, (float*)d_out);
}

// round 8
// speedup vs baseline: 5.6798x; 2.3333x over previous
#include <cuda_runtime.h>
#include <cuda_fp16.h>
#include <cstdint>

// Problem: K=8192 rows, L=128 steps, D=64
#define NTH  512
#define NBLK 128
#define LT   128

// ---- smem byte offsets ----
#define HROW    144        // 64 fp16 = 128B data + 16B pad per row
#define HB_OFF  0          // 2 x 64 x 144 = 18432
#define HB_BUF  9216
#define X_OFF   18432      // 64 x 132 f32 = 33792
#define XS      132
#define BL_OFF  52224      // W_lo frags: 8wn x 4kk x 4nt x 32l x 8B = 32768
#define HF_OFF  84992      // final h [64][66] f32 = 16896
#define CF_OFF  101888     // final c [64][66] f32 = 16896
#define VCB_OFF 118784     // float2[256] = 2048
#define RED_OFF 120832     // 2 x 1024 f32 = 8192
#define SMEM_BYTES 129024
// tail overlays (recurrence-only regions reused)
#define WA_OFF  0
#define WF_OFF  X_OFF
#define HS2_OFF BL_OFF

typedef unsigned long long u64;

__device__ float g_Pfc[NBLK * 64];
__device__ float g_Phs[NBLK * 64];

__device__ __forceinline__ uint32_t smem_u32(const void* p) {
    uint32_t a;
    asm("{ .reg .u64 t; cvta.to.shared.u64 t, %1; cvt.u32.u64 %0, t; }" : "=r"(a) : "l"(p));
    return a;
}
__device__ __forceinline__ void ldmx4(uint32_t* r, uint32_t addr) {
    asm volatile("ldmatrix.sync.aligned.m8n8.x4.shared.b16 {%0,%1,%2,%3}, [%4];"
                 : "=r"(r[0]), "=r"(r[1]), "=r"(r[2]), "=r"(r[3]) : "r"(addr));
}
__device__ __forceinline__ void mma16816(float* d, const uint32_t* a, const uint32_t* b) {
    asm volatile("mma.sync.aligned.m16n8k16.row.col.f32.f16.f16.f32 "
                 "{%0,%1,%2,%3}, {%4,%5,%6,%7}, {%8,%9}, {%0,%1,%2,%3};"
                 : "+f"(d[0]), "+f"(d[1]), "+f"(d[2]), "+f"(d[3])
                 : "r"(a[0]), "r"(a[1]), "r"(a[2]), "r"(a[3]), "r"(b[0]), "r"(b[1]));
}
__device__ __forceinline__ uint32_t pkh2(__half lo, __half hi) {
    return ((uint32_t)__half_as_ushort(hi) << 16) | __half_as_ushort(lo);
}
// fast activations for the recurrence (1 MUFU each)
__device__ __forceinline__ float tanh_a(float x) {
    float r;
    asm("tanh.approx.f32 %0, %1;" : "=f"(r) : "f"(x));
    return r;
}
__device__ __forceinline__ float sig_a(float x) {
    return fmaf(tanh_a(0.5f * x), 0.5f, 0.5f);
}
// accurate versions for tail / finale
__device__ __forceinline__ float sigf(float x)   { return 1.0f / (1.0f + __expf(-x)); }
__device__ __forceinline__ float tanh_f(float x) { float e = __expf(2.0f * x); return 1.0f - 2.0f / (e + 1.0f); }

#define BARW(id) asm volatile("bar.sync %0, 256;" :: "r"(id) : "memory")

__global__ __launch_bounds__(NTH, 1)
void lstm_main(const float* __restrict__ x,
               const float* __restrict__ W_num, const float* __restrict__ b_num,
               const float* __restrict__ W_ih,  const float* __restrict__ W_hh,
               const float* __restrict__ b_ih,  const float* __restrict__ b_hh,
               const float* __restrict__ W_aout, const float* __restrict__ b_aout,
               const float* __restrict__ W_fh,   const float* __restrict__ b_fh)
{
    extern __shared__ char smem[];
    const uint32_t sb = smem_u32(smem);

    float*  x_s   = (float*)(smem + X_OFF);
    float*  hf_s  = (float*)(smem + HF_OFF);
    float*  cf_s  = (float*)(smem + CF_OFF);
    float2* vcb_s = (float2*)(smem + VCB_OFF);
    float*  red   = (float*)(smem + RED_OFF);

    const int tid  = threadIdx.x;
    const int l    = tid & 31;
    const int wid  = tid >> 5;
    const int wm   = wid >> 3;          // row-group: rows wm*32 .. +31
    const int wn   = wid & 7;           // unit-group: units wn*8 .. +7
    const int c    = l & 3;
    const int quad = l >> 2;
    const int u0   = 8 * wn + 2 * c;    // this thread's unit pair u0, u0+1
    const int barid = 1 + wm;           // per-row-group named barrier

    // ---- zero h buffer 0 (h(0)=0) ----
    for (int i = tid; i < HB_BUF / 4; i += NTH) ((uint32_t*)(smem + HB_OFF))[i] = 0u;

    // ---- stage x rows (padded stride, bank-spread) ----
    {
        const float* xg = x + (size_t)blockIdx.x * (64 * LT);
        for (int i = tid; i < 64 * LT; i += NTH) x_s[(i >> 7) * XS + (i & 127)] = xg[i];
    }

    // ---- rank-1 input precompute, stored at remapped gate index m ----
    // orig gate g = q*64+u (q: 0=i,1=f,2=g,3=o)
    // m = (q>>1)*128 + (u>>3)*16 + (u&1)*8 + ((u>>1)&3)*2 + (q&1)
    if (tid < 256) {
        int g = tid;
        const float* wr = W_ih + g * 128;   // (256,128); first 64 cols used
        float v = 0.0f, cb = 0.0f;
        #pragma unroll 8
        for (int j = 0; j < 64; ++j) {
            float ww = wr[j];
            v  = fmaf(ww, W_num[j], v);
            cb = fmaf(ww, b_num[j], cb);
        }
        int q = g >> 6, u = g & 63;
        int m = (q >> 1) * 128 + (u >> 3) * 16 + (u & 1) * 8 + ((u >> 1) & 3) * 2 + (q & 1);
        vcb_s[m] = make_float2(v, cb + b_ih[g] + b_hh[g]);
    }

    // ---- W fragments: hi in regs, lo in smem ----
    uint32_t Bh[4][4][2];
    #pragma unroll
    for (int nt = 0; nt < 4; ++nt) {
        int u = 8 * wn + 2 * (quad >> 1) + (nt & 1);
        int q = (nt >> 1) * 2 + (quad & 1);
        const float* wr = W_hh + (q * 64 + u) * 64;
        #pragma unroll
        for (int kk = 0; kk < 4; ++kk) {
            int j0 = kk * 16 + 2 * c;
            float w00 = wr[j0], w01 = wr[j0 + 1], w10 = wr[j0 + 8], w11 = wr[j0 + 9];
            __half a00 = __float2half(w00), a01 = __float2half(w01);
            __half a10 = __float2half(w10), a11 = __float2half(w11);
            Bh[nt][kk][0] = pkh2(a00, a01);
            Bh[nt][kk][1] = pkh2(a10, a11);
            if (wm == 0) {
                __half l00 = __float2half(w00 - __half2float(a00));
                __half l01 = __float2half(w01 - __half2float(a01));
                __half l10 = __float2half(w10 - __half2float(a10));
                __half l11 = __float2half(w11 - __half2float(a11));
                u64 v = ((u64)pkh2(l10, l11) << 32) | pkh2(l00, l01);
                *(u64*)(smem + BL_OFF + ((((wn * 4 + kk) * 4 + nt) * 32) + l) * 8) = v;
            }
        }
    }
    __syncthreads();

    float cst[2][2][2];   // [mt][rr][z]
    #pragma unroll
    for (int mt = 0; mt < 2; ++mt)
        #pragma unroll
        for (int rr = 0; rr < 2; ++rr) { cst[mt][rr][0] = 0.0f; cst[mt][rr][1] = 0.0f; }

    const uint32_t abase = sb + HB_OFF + (wm * 32 + (l & 15)) * HROW + (l >> 4) * 16;

    // ================= recurrence: 128 sequential steps =================
    // Row-groups (wm) are fully independent: per-step sync is a 256-thread named barrier.
    for (int t = 0; t < LT; ++t) {
        // --- init D with rank-1 x-term + fused bias ---
        float D[2][4][4];
        float xv[2][2];
        #pragma unroll
        for (int mt = 0; mt < 2; ++mt) {
            int ra = wm * 32 + mt * 16 + quad;
            xv[mt][0] = x_s[ra * XS + t];
            xv[mt][1] = x_s[(ra + 8) * XS + t];
        }
        #pragma unroll
        for (int nt = 0; nt < 4; ++nt) {
            int mb = (nt >> 1) * 128 + wn * 16 + (nt & 1) * 8 + 2 * c;
            float2 p0 = vcb_s[mb], p1 = vcb_s[mb + 1];
            #pragma unroll
            for (int mt = 0; mt < 2; ++mt) {
                D[mt][nt][0] = fmaf(xv[mt][0], p0.x, p0.y);
                D[mt][nt][1] = fmaf(xv[mt][0], p1.x, p1.y);
                D[mt][nt][2] = fmaf(xv[mt][1], p0.x, p0.y);
                D[mt][nt][3] = fmaf(xv[mt][1], p1.x, p1.y);
            }
        }

        // --- D += h @ W^T : fp16 mma, W 2-way split (hi regs, lo smem) ---
        const uint32_t ab = abase + (t & 1) * HB_BUF;
        #pragma unroll
        for (int kk = 0; kk < 4; ++kk) {
            uint32_t Ah0[4], Ah1[4];
            ldmx4(Ah0, ab + kk * 32);
            ldmx4(Ah1, ab + 16 * HROW + kk * 32);
            #pragma unroll
            for (int nt = 0; nt < 4; ++nt) {
                u64 blv = *(const u64*)(smem + BL_OFF + ((((wn * 4 + kk) * 4 + nt) * 32) + l) * 8);
                uint32_t bl[2] = { (uint32_t)blv, (uint32_t)(blv >> 32) };
                mma16816(D[0][nt], Ah0, Bh[nt][kk]);
                mma16816(D[1][nt], Ah1, Bh[nt][kk]);
                mma16816(D[0][nt], Ah0, bl);
                mma16816(D[1][nt], Ah1, bl);
            }
        }

        // --- epilogue: fast activations, packed h store ---
        char* hnext = smem + HB_OFF + ((t + 1) & 1) * HB_BUF;
        #pragma unroll
        for (int mt = 0; mt < 2; ++mt)
            #pragma unroll
            for (int rr = 0; rr < 2; ++rr) {
                int row = wm * 32 + mt * 16 + quad + 8 * rr;
                float hz[2];
                #pragma unroll
                for (int z = 0; z < 2; ++z) {
                    float gi = D[mt][z][2 * rr];
                    float gf = D[mt][z][2 * rr + 1];
                    float gg = D[mt][2 + z][2 * rr];
                    float go = D[mt][2 + z][2 * rr + 1];
                    float cn = sig_a(gf) * cst[mt][rr][z] + sig_a(gi) * tanh_a(gg);
                    cst[mt][rr][z] = cn;
                    hz[z] = sig_a(go) * tanh_a(cn);
                    if (t == LT - 1) {
                        hf_s[row * 66 + u0 + z] = hz[z];
                        cf_s[row * 66 + u0 + z] = cn;
                    }
                }
                if (t < LT - 1) {
                    __half2 hp = __floats2half2_rn(hz[0], hz[1]);
                    *(uint32_t*)(hnext + row * HROW + 2 * u0) = *(uint32_t*)&hp;
                }
            }
        BARW(barid);
    }
    __syncthreads();   // join row-groups before tail overlays h-buffer region

    // ================= tail =================
    float* wa  = (float*)(smem + WA_OFF);    // [j*66+u]
    float* wf  = (float*)(smem + WF_OFF);
    float* hs2 = (float*)(smem + HS2_OFF);   // h_hat staging [r][66]
    for (int idx = tid; idx < 4096; idx += NTH) {
        int u = idx >> 6, j = idx & 63;
        wa[j * 66 + u] = W_aout[idx];
        wf[j * 66 + u] = W_fh[idx];
    }
    __syncthreads();

    const int tw = wid;            // 16 warps
    const int r0 = tw * 4;         // rows r0..r0+3
    const int tu = 2 * l;          // units tu, tu+1

    // h_hat = h @ W_aout^T + b_aout
    float hh2[2][4];
    {
        float b0 = b_aout[tu], b1 = b_aout[tu + 1];
        #pragma unroll
        for (int rr = 0; rr < 4; ++rr) { hh2[0][rr] = b0; hh2[1][rr] = b1; }
        #pragma unroll 8
        for (int j = 0; j < 64; ++j) {
            float w0 = wa[j * 66 + tu], w1 = wa[j * 66 + tu + 1];
            #pragma unroll
            for (int rr = 0; rr < 4; ++rr) {
                float hj = hf_s[(r0 + rr) * 66 + j];
                hh2[0][rr] = fmaf(hj, w0, hh2[0][rr]);
                hh2[1][rr] = fmaf(hj, w1, hh2[1][rr]);
            }
        }
        #pragma unroll
        for (int rr = 0; rr < 4; ++rr) {
            hs2[(r0 + rr) * 66 + tu]     = hh2[0][rr];
            hs2[(r0 + rr) * 66 + tu + 1] = hh2[1][rr];
        }
    }
    __syncthreads();

    // f = h_hat @ W_fh^T + b_fh ; partial sums
    float fv2[2][4];
    {
        float b0 = b_fh[tu], b1 = b_fh[tu + 1];
        #pragma unroll
        for (int rr = 0; rr < 4; ++rr) { fv2[0][rr] = b0; fv2[1][rr] = b1; }
        #pragma unroll 8
        for (int j = 0; j < 64; ++j) {
            float w0 = wf[j * 66 + tu], w1 = wf[j * 66 + tu + 1];
            #pragma unroll
            for (int rr = 0; rr < 4; ++rr) {
                float hj = hs2[(r0 + rr) * 66 + j];
                fv2[0][rr] = fmaf(hj, w0, fv2[0][rr]);
                fv2[1][rr] = fmaf(hj, w1, fv2[1][rr]);
            }
        }
    }

    float fc0 = 0.0f, fc1 = 0.0f, hs0 = 0.0f, hs1 = 0.0f;
    #pragma unroll
    for (int rr = 0; rr < 4; ++rr) {
        fc0 += sigf(fv2[0][rr]) * cf_s[(r0 + rr) * 66 + tu];
        fc1 += sigf(fv2[1][rr]) * cf_s[(r0 + rr) * 66 + tu + 1];
        hs0 += hh2[0][rr];
        hs1 += hh2[1][rr];
    }
    red[tw * 64 + tu]            = fc0;
    red[tw * 64 + tu + 1]        = fc1;
    red[1024 + tw * 64 + tu]     = hs0;
    red[1024 + tw * 64 + tu + 1] = hs1;
    __syncthreads();

    if (tid < 64) {
        float a = 0.0f, b = 0.0f;
        #pragma unroll
        for (int g = 0; g < 16; ++g) {
            a += red[g * 64 + tid];
            b += red[1024 + g * 64 + tid];
        }
        g_Pfc[blockIdx.x * 64 + tid] = a;
        g_Phs[blockIdx.x * 64 + tid] = b;
    }
}

// ================= finale: reduce partials + object-cell head =================
__global__ void lstm_final(const float* __restrict__ W_iouh, const float* __restrict__ b_iouh,
                           const float* __restrict__ W_oout, const float* __restrict__ b_oout,
                           float* __restrict__ out)
{
    __shared__ float s_fc[4][64];
    __shared__ float s_hs[4][64];
    __shared__ float hsb[64];
    __shared__ float hob[64];

    int tid = threadIdx.x;      // 256 threads
    int q = tid >> 6, u = tid & 63;

    float fc = 0.0f, hs = 0.0f;
    #pragma unroll 8
    for (int b = q; b < NBLK; b += 4) {
        fc += g_Pfc[b * 64 + u];
        hs += g_Phs[b * 64 + u];
    }
    s_fc[q][u] = fc;
    s_hs[q][u] = hs;
    __syncthreads();

    float fct = 0.0f;
    if (tid < 64) {
        float hst = 0.0f;
        #pragma unroll
        for (int k = 0; k < 4; ++k) { fct += s_fc[k][tid]; hst += s_hs[k][tid]; }
        hsb[tid] = hst;
    }
    __syncthreads();

    if (tid < 64) {
        float ig = b_iouh[tid], og = b_iouh[64 + tid], ug = b_iouh[128 + tid];
        #pragma unroll 8
        for (int j = 0; j < 64; ++j) {
            float h = hsb[j];
            ig = fmaf(h, W_iouh[tid * 64 + j],         ig);
            og = fmaf(h, W_iouh[(64 + tid) * 64 + j],  og);
            ug = fmaf(h, W_iouh[(128 + tid) * 64 + j], ug);
        }
        float c_obj = sigf(ig) * tanh_f(ug) + fct;
        float h_obj = sigf(og) * tanh_f(c_obj);
        hob[tid] = h_obj;
        out[64 + tid] = c_obj;
    }
    __syncthreads();

    if (tid < 64) {
        float hh = b_oout[tid];
        #pragma unroll 8
        for (int j = 0; j < 64; ++j)
            hh = fmaf(hob[j], W_oout[tid * 64 + j], hh);
        out[tid] = hh;
    }
}

extern "C" void kernel_launch(void* const* d_in, const int* in_sizes, int n_in,
                              void* d_out, int out_size)
{
    const float* x      = (const float*)d_in[0];
    const float* W_num  = (const float*)d_in[1];
    const float* b_num  = (const float*)d_in[2];
    const float* W_ih   = (const float*)d_in[3];
    const float* W_hh   = (const float*)d_in[4];
    const float* b_ih   = (const float*)d_in[5];
    const float* b_hh   = (const float*)d_in[6];
    const float* W_aout = (const float*)d_in[7];
    const float* b_aout = (const float*)d_in[8];
    const float* W_fh   = (const float*)d_in[9];
    const float* b_fh   = (const float*)d_in[10];
    const float* W_iouh = (const float*)d_in[11];
    const float* b_iouh = (const float*)d_in[12];
    const float* W_oout = (const float*)d_in[13];
    const float* b_oout = (const float*)d_in[14];

    (void)in_sizes; (void)n_in; (void)out_size;

    cudaFuncSetAttribute(lstm_main, cudaFuncAttributeMaxDynamicSharedMemorySize, SMEM_BYTES);

    lstm_main<<<NBLK, NTH, SMEM_BYTES>>>(x, W_num, b_num, W_ih, W_hh, b_ih, b_hh,
                                         W_aout, b_aout, W_fh, b_fh);
    lstm_final<<<1, 256>>>(W_iouh, b_iouh, W_oout, b_oout, (float*)d_out);
}

// round 9
// speedup vs baseline: 9.3443x; 1.6452x over previous
#include <cuda_runtime.h>
#include <cuda_fp16.h>
#include <cstdint>

// Problem: K=8192 rows, L=128 steps, D=64
#define NTH  512
#define NBLK 128
#define LT   128

// ---- smem byte offsets ----
#define HROW    144        // 64 fp16 = 128B data + 16B pad per row
#define HB_OFF  0          // 2 x 64 x 144 = 18432
#define HB_BUF  9216
#define X_OFF   18432      // 64 x 132 f32 = 33792
#define XS      132
#define HF_OFF  52224      // final h [64][66] f32 = 16896
#define CF_OFF  69120      // final c [64][66] f32 = 16896
#define VCB_OFF 86016      // float2[256] = 2048
#define RED_OFF 88064      // 2 x 1024 f32 = 8192
#define HS2_OFF 96256      // tail h_hat staging [64][66] f32 = 16896
#define SMEM_BYTES 113152
// tail overlays (recurrence-only regions reused)
#define WA_OFF  0
#define WF_OFF  X_OFF

typedef unsigned long long u64;

__device__ float g_Pfc[NBLK * 64];
__device__ float g_Phs[NBLK * 64];

__device__ __forceinline__ uint32_t smem_u32(const void* p) {
    uint32_t a;
    asm("{ .reg .u64 t; cvta.to.shared.u64 t, %1; cvt.u32.u64 %0, t; }" : "=r"(a) : "l"(p));
    return a;
}
__device__ __forceinline__ void ldmx4(uint32_t* r, uint32_t addr) {
    asm volatile("ldmatrix.sync.aligned.m8n8.x4.shared.b16 {%0,%1,%2,%3}, [%4];"
                 : "=r"(r[0]), "=r"(r[1]), "=r"(r[2]), "=r"(r[3]) : "r"(addr));
}
__device__ __forceinline__ void mma16816(float* d, const uint32_t* a, const uint32_t* b) {
    asm volatile("mma.sync.aligned.m16n8k16.row.col.f32.f16.f16.f32 "
                 "{%0,%1,%2,%3}, {%4,%5,%6,%7}, {%8,%9}, {%0,%1,%2,%3};"
                 : "+f"(d[0]), "+f"(d[1]), "+f"(d[2]), "+f"(d[3])
                 : "r"(a[0]), "r"(a[1]), "r"(a[2]), "r"(a[3]), "r"(b[0]), "r"(b[1]));
}
__device__ __forceinline__ uint32_t pkh2(__half lo, __half hi) {
    return ((uint32_t)__half_as_ushort(hi) << 16) | __half_as_ushort(lo);
}
// fast activations for the recurrence (1 MUFU each)
__device__ __forceinline__ float tanh_a(float x) {
    float r;
    asm("tanh.approx.f32 %0, %1;" : "=f"(r) : "f"(x));
    return r;
}
__device__ __forceinline__ float sig_a(float x) {
    return fmaf(tanh_a(0.5f * x), 0.5f, 0.5f);
}
// accurate versions for tail / finale
__device__ __forceinline__ float sigf(float x)   { return 1.0f / (1.0f + __expf(-x)); }
__device__ __forceinline__ float tanh_f(float x) { float e = __expf(2.0f * x); return 1.0f - 2.0f / (e + 1.0f); }

#define BARW(id) asm volatile("bar.sync %0, 256;" :: "r"(id) : "memory")

__global__ __launch_bounds__(NTH, 1)
void lstm_main(const float* __restrict__ x,
               const float* __restrict__ W_num, const float* __restrict__ b_num,
               const float* __restrict__ W_ih,  const float* __restrict__ W_hh,
               const float* __restrict__ b_ih,  const float* __restrict__ b_hh,
               const float* __restrict__ W_aout, const float* __restrict__ b_aout,
               const float* __restrict__ W_fh,   const float* __restrict__ b_fh)
{
    extern __shared__ char smem[];
    const uint32_t sb = smem_u32(smem);

    float*  x_s   = (float*)(smem + X_OFF);
    float*  hf_s  = (float*)(smem + HF_OFF);
    float*  cf_s  = (float*)(smem + CF_OFF);
    float2* vcb_s = (float2*)(smem + VCB_OFF);
    float*  red   = (float*)(smem + RED_OFF);

    const int tid  = threadIdx.x;
    const int l    = tid & 31;
    const int wid  = tid >> 5;
    const int wm   = wid >> 3;          // row-group: rows wm*32 .. +31
    const int wn   = wid & 7;           // unit-group: units wn*8 .. +7
    const int c    = l & 3;
    const int quad = l >> 2;
    const int u0   = 8 * wn + 2 * c;    // this thread's unit pair u0, u0+1
    const int barid = 1 + wm;           // per-row-group named barrier

    // ---- zero h buffer 0 (h(0)=0) ----
    for (int i = tid; i < HB_BUF / 4; i += NTH) ((uint32_t*)(smem + HB_OFF))[i] = 0u;

    // ---- stage x rows (padded stride, bank-spread) ----
    {
        const float* xg = x + (size_t)blockIdx.x * (64 * LT);
        for (int i = tid; i < 64 * LT; i += NTH) x_s[(i >> 7) * XS + (i & 127)] = xg[i];
    }

    // ---- rank-1 input precompute, stored at remapped gate index m ----
    // orig gate g = q*64+u (q: 0=i,1=f,2=g,3=o)
    // m = (q>>1)*128 + (u>>3)*16 + (u&1)*8 + ((u>>1)&3)*2 + (q&1)
    if (tid < 256) {
        int g = tid;
        const float* wr = W_ih + g * 128;   // (256,128); first 64 cols used
        float v = 0.0f, cb = 0.0f;
        #pragma unroll 8
        for (int j = 0; j < 64; ++j) {
            float ww = wr[j];
            v  = fmaf(ww, W_num[j], v);
            cb = fmaf(ww, b_num[j], cb);
        }
        int q = g >> 6, u = g & 63;
        int m = (q >> 1) * 128 + (u >> 3) * 16 + (u & 1) * 8 + ((u >> 1) & 3) * 2 + (q & 1);
        vcb_s[m] = make_float2(v, cb + b_ih[g] + b_hh[g]);
    }

    // ---- W fragments (fp16) in registers ----
    uint32_t Bh[4][4][2];
    #pragma unroll
    for (int nt = 0; nt < 4; ++nt) {
        int u = 8 * wn + 2 * (quad >> 1) + (nt & 1);
        int q = (nt >> 1) * 2 + (quad & 1);
        const float* wr = W_hh + (q * 64 + u) * 64;
        #pragma unroll
        for (int kk = 0; kk < 4; ++kk) {
            int j0 = kk * 16 + 2 * c;
            Bh[nt][kk][0] = pkh2(__float2half(wr[j0]),     __float2half(wr[j0 + 1]));
            Bh[nt][kk][1] = pkh2(__float2half(wr[j0 + 8]), __float2half(wr[j0 + 9]));
        }
    }
    __syncthreads();

    // hoist step-invariant gate constants into registers
    float2 P0[4], P1[4];
    #pragma unroll
    for (int nt = 0; nt < 4; ++nt) {
        int mb = (nt >> 1) * 128 + wn * 16 + (nt & 1) * 8 + 2 * c;
        P0[nt] = vcb_s[mb];
        P1[nt] = vcb_s[mb + 1];
    }

    float cst[2][2][2];   // [mt][rr][z]
    #pragma unroll
    for (int mt = 0; mt < 2; ++mt)
        #pragma unroll
        for (int rr = 0; rr < 2; ++rr) { cst[mt][rr][0] = 0.0f; cst[mt][rr][1] = 0.0f; }

    const uint32_t abase = sb + HB_OFF + (wm * 32 + (l & 15)) * HROW + (l >> 4) * 16;

    // ================= recurrence: 128 sequential steps =================
    for (int t = 0; t < LT; ++t) {
        // --- init D with rank-1 x-term + fused bias ---
        float D[2][4][4];
        float xv[2][2];
        #pragma unroll
        for (int mt = 0; mt < 2; ++mt) {
            int ra = wm * 32 + mt * 16 + quad;
            xv[mt][0] = x_s[ra * XS + t];
            xv[mt][1] = x_s[(ra + 8) * XS + t];
        }
        #pragma unroll
        for (int nt = 0; nt < 4; ++nt) {
            float2 p0 = P0[nt], p1 = P1[nt];
            #pragma unroll
            for (int mt = 0; mt < 2; ++mt) {
                D[mt][nt][0] = fmaf(xv[mt][0], p0.x, p0.y);
                D[mt][nt][1] = fmaf(xv[mt][0], p1.x, p1.y);
                D[mt][nt][2] = fmaf(xv[mt][1], p0.x, p0.y);
                D[mt][nt][3] = fmaf(xv[mt][1], p1.x, p1.y);
            }
        }

        // --- D += h @ W^T : fp16 mma (single pass) ---
        const uint32_t ab = abase + (t & 1) * HB_BUF;
        #pragma unroll
        for (int kk = 0; kk < 4; ++kk) {
            uint32_t Ah0[4], Ah1[4];
            ldmx4(Ah0, ab + kk * 32);
            ldmx4(Ah1, ab + 16 * HROW + kk * 32);
            #pragma unroll
            for (int nt = 0; nt < 4; ++nt) {
                mma16816(D[0][nt], Ah0, Bh[nt][kk]);
                mma16816(D[1][nt], Ah1, Bh[nt][kk]);
            }
        }

        // --- epilogue: fast activations, packed h store ---
        char* hnext = smem + HB_OFF + ((t + 1) & 1) * HB_BUF;
        #pragma unroll
        for (int mt = 0; mt < 2; ++mt)
            #pragma unroll
            for (int rr = 0; rr < 2; ++rr) {
                int row = wm * 32 + mt * 16 + quad + 8 * rr;
                float hz[2];
                #pragma unroll
                for (int z = 0; z < 2; ++z) {
                    float gi = D[mt][z][2 * rr];
                    float gf = D[mt][z][2 * rr + 1];
                    float gg = D[mt][2 + z][2 * rr];
                    float go = D[mt][2 + z][2 * rr + 1];
                    float cn = sig_a(gf) * cst[mt][rr][z] + sig_a(gi) * tanh_a(gg);
                    cst[mt][rr][z] = cn;
                    hz[z] = sig_a(go) * tanh_a(cn);
                    if (t == LT - 1) {
                        hf_s[row * 66 + u0 + z] = hz[z];
                        cf_s[row * 66 + u0 + z] = cn;
                    }
                }
                if (t < LT - 1) {
                    __half2 hp = __floats2half2_rn(hz[0], hz[1]);
                    *(uint32_t*)(hnext + row * HROW + 2 * u0) = *(uint32_t*)&hp;
                }
            }
        BARW(barid);
    }
    __syncthreads();   // join row-groups before tail overlays

    // ================= tail =================
    float* wa  = (float*)(smem + WA_OFF);    // [j*66+u]
    float* wf  = (float*)(smem + WF_OFF);
    float* hs2 = (float*)(smem + HS2_OFF);   // h_hat staging [r][66]
    for (int idx = tid; idx < 4096; idx += NTH) {
        int u = idx >> 6, j = idx & 63;
        wa[j * 66 + u] = W_aout[idx];
        wf[j * 66 + u] = W_fh[idx];
    }
    __syncthreads();

    const int tw = wid;            // 16 warps
    const int r0 = tw * 4;         // rows r0..r0+3
    const int tu = 2 * l;          // units tu, tu+1

    // h_hat = h @ W_aout^T + b_aout
    float hh2[2][4];
    {
        float b0 = b_aout[tu], b1 = b_aout[tu + 1];
        #pragma unroll
        for (int rr = 0; rr < 4; ++rr) { hh2[0][rr] = b0; hh2[1][rr] = b1; }
        #pragma unroll 8
        for (int j = 0; j < 64; ++j) {
            float w0 = wa[j * 66 + tu], w1 = wa[j * 66 + tu + 1];
            #pragma unroll
            for (int rr = 0; rr < 4; ++rr) {
                float hj = hf_s[(r0 + rr) * 66 + j];
                hh2[0][rr] = fmaf(hj, w0, hh2[0][rr]);
                hh2[1][rr] = fmaf(hj, w1, hh2[1][rr]);
            }
        }
        #pragma unroll
        for (int rr = 0; rr < 4; ++rr) {
            hs2[(r0 + rr) * 66 + tu]     = hh2[0][rr];
            hs2[(r0 + rr) * 66 + tu + 1] = hh2[1][rr];
        }
    }
    __syncthreads();

    // f = h_hat @ W_fh^T + b_fh ; partial sums
    float fv2[2][4];
    {
        float b0 = b_fh[tu], b1 = b_fh[tu + 1];
        #pragma unroll
        for (int rr = 0; rr < 4; ++rr) { fv2[0][rr] = b0; fv2[1][rr] = b1; }
        #pragma unroll 8
        for (int j = 0; j < 64; ++j) {
            float w0 = wf[j * 66 + tu], w1 = wf[j * 66 + tu + 1];
            #pragma unroll
            for (int rr = 0; rr < 4; ++rr) {
                float hj = hs2[(r0 + rr) * 66 + j];
                fv2[0][rr] = fmaf(hj, w0, fv2[0][rr]);
                fv2[1][rr] = fmaf(hj, w1, fv2[1][rr]);
            }
        }
    }

    float fc0 = 0.0f, fc1 = 0.0f, hs0 = 0.0f, hs1 = 0.0f;
    #pragma unroll
    for (int rr = 0; rr < 4; ++rr) {
        fc0 += sigf(fv2[0][rr]) * cf_s[(r0 + rr) * 66 + tu];
        fc1 += sigf(fv2[1][rr]) * cf_s[(r0 + rr) * 66 + tu + 1];
        hs0 += hh2[0][rr];
        hs1 += hh2[1][rr];
    }
    red[tw * 64 + tu]            = fc0;
    red[tw * 64 + tu + 1]        = fc1;
    red[1024 + tw * 64 + tu]     = hs0;
    red[1024 + tw * 64 + tu + 1] = hs1;
    __syncthreads();

    if (tid < 64) {
        float a = 0.0f, b = 0.0f;
        #pragma unroll
        for (int g = 0; g < 16; ++g) {
            a += red[g * 64 + tid];
            b += red[1024 + g * 64 + tid];
        }
        g_Pfc[blockIdx.x * 64 + tid] = a;
        g_Phs[blockIdx.x * 64 + tid] = b;
    }
}

// ================= finale: parallel reduce + object-cell head (1024 thr) =================
__global__ __launch_bounds__(1024, 1)
void lstm_final(const float* __restrict__ W_iouh, const float* __restrict__ b_iouh,
                const float* __restrict__ W_oout, const float* __restrict__ b_oout,
                float* __restrict__ out)
{
    __shared__ float s_fc[16][64];
    __shared__ float s_hs[16][64];
    __shared__ float hsb[64];
    __shared__ float fcb[64];
    __shared__ float s_g[192][4];
    __shared__ float iouv[192];
    __shared__ float hob[64];
    __shared__ float s_o[64][16];

    const int tid = threadIdx.x;   // 1024
    const int q = tid >> 6, u = tid & 63;

    // phase 1: reduce per-block partials (128 blocks -> 16 -> 1)
    float fc = 0.0f, hs = 0.0f;
    #pragma unroll
    for (int b = q; b < NBLK; b += 16) {
        fc += g_Pfc[b * 64 + u];
        hs += g_Phs[b * 64 + u];
    }
    s_fc[q][u] = fc;
    s_hs[q][u] = hs;
    __syncthreads();
    if (tid < 64) {
        float a = 0.0f, b = 0.0f;
        #pragma unroll
        for (int k = 0; k < 16; ++k) { a += s_fc[k][tid]; b += s_hs[k][tid]; }
        fcb[tid] = a;
        hsb[tid] = b;
    }
    __syncthreads();

    // phase 2: iou = hsb @ W_iouh^T + b_iouh  (192 outputs x 4 K-chunks)
    if (tid < 768) {
        int g = tid >> 2, ch = tid & 3;
        const float* wr = W_iouh + g * 64 + ch * 16;
        const float* hp = hsb + ch * 16;
        float s = 0.0f;
        #pragma unroll
        for (int j = 0; j < 16; ++j) s = fmaf(hp[j], wr[j], s);
        s_g[g][ch] = s;
    }
    __syncthreads();
    if (tid < 192)
        iouv[tid] = s_g[tid][0] + s_g[tid][1] + s_g[tid][2] + s_g[tid][3] + b_iouh[tid];
    __syncthreads();

    // phase 3: object cell
    if (tid < 64) {
        float c_obj = sigf(iouv[tid]) * tanh_f(iouv[128 + tid]) + fcb[tid];
        float h_obj = sigf(iouv[64 + tid]) * tanh_f(c_obj);
        hob[tid] = h_obj;
        out[64 + tid] = c_obj;
    }
    __syncthreads();

    // phase 4: out[0:64] = hob @ W_oout^T + b_oout (64 outputs x 16 K-chunks)
    {
        int uo = tid >> 4, ch = tid & 15;
        const float* wr = W_oout + uo * 64 + ch * 4;
        const float* hp = hob + ch * 4;
        float s = 0.0f;
        #pragma unroll
        for (int j = 0; j < 4; ++j) s = fmaf(hp[j], wr[j], s);
        s_o[uo][ch] = s;
    }
    __syncthreads();
    if (tid < 64) {
        float s = b_oout[tid];
        #pragma unroll
        for (int k = 0; k < 16; ++k) s += s_o[tid][k];
        out[tid] = s;
    }
}

extern "C" void kernel_launch(void* const* d_in, const int* in_sizes, int n_in,
                              void* d_out, int out_size)
{
    const float* x      = (const float*)d_in[0];
    const float* W_num  = (const float*)d_in[1];
    const float* b_num  = (const float*)d_in[2];
    const float* W_ih   = (const float*)d_in[3];
    const float* W_hh   = (const float*)d_in[4];
    const float* b_ih   = (const float*)d_in[5];
    const float* b_hh   = (const float*)d_in[6];
    const float* W_aout = (const float*)d_in[7];
    const float* b_aout = (const float*)d_in[8];
    const float* W_fh   = (const float*)d_in[9];
    const float* b_fh   = (const float*)d_in[10];
    const float* W_iouh = (const float*)d_in[11];
    const float* b_iouh = (const float*)d_in[12];
    const float* W_oout = (const float*)d_in[13];
    const float* b_oout = (const float*)d_in[14];

    (void)in_sizes; (void)n_in; (void)out_size;

    cudaFuncSetAttribute(lstm_main, cudaFuncAttributeMaxDynamicSharedMemorySize, SMEM_BYTES);

    lstm_main<<<NBLK, NTH, SMEM_BYTES>>>(x, W_num, b_num, W_ih, W_hh, b_ih, b_hh,
                                         W_aout, b_aout, W_fh, b_fh);
    lstm_final<<<1, 1024>>>(W_iouh, b_iouh, W_oout, b_oout, (float*)d_out);
}

// round 10
// speedup vs baseline: 9.5417x; 1.0211x over previous
#include <cuda_runtime.h>
#include <cuda_fp16.h>
#include <cstdint>

// Problem: K=8192 rows, L=128 steps, D=64
#define NTH  512
#define NBLK 128
#define LT   128

// ---- smem byte offsets ----
#define HROW    144        // 64 fp16 = 128B data + 16B pad per row
#define HB_OFF  0          // 2 x 64 x 144 = 18432
#define HB_BUF  9216
#define X_OFF   18432      // 64 x 132 f32 = 33792
#define XS      132
#define HF_OFF  52224      // final h [64][66] f32 = 16896
#define CF_OFF  69120      // final c [64][66] f32 = 16896
#define VCB_OFF 86016      // float2[256] = 2048
#define RED_OFF 88064      // 2 x 1024 f32 = 8192
#define HS2_OFF 96256      // tail h_hat staging [64][66] f32 = 16896
#define SMEM_BYTES 113152
// tail overlays (recurrence-only regions reused)
#define WA_OFF  0
#define WF_OFF  X_OFF

typedef unsigned long long u64;

__device__ float g_Pfc[NBLK * 64];
__device__ float g_Phs[NBLK * 64];

__device__ __forceinline__ uint32_t smem_u32(const void* p) {
    uint32_t a;
    asm("{ .reg .u64 t; cvta.to.shared.u64 t, %1; cvt.u32.u64 %0, t; }" : "=r"(a) : "l"(p));
    return a;
}
__device__ __forceinline__ void ldmx4(uint32_t* r, uint32_t addr) {
    asm volatile("ldmatrix.sync.aligned.m8n8.x4.shared.b16 {%0,%1,%2,%3}, [%4];"
                 : "=r"(r[0]), "=r"(r[1]), "=r"(r[2]), "=r"(r[3]) : "r"(addr));
}
__device__ __forceinline__ void mma16816(float* d, const uint32_t* a, const uint32_t* b) {
    asm volatile("mma.sync.aligned.m16n8k16.row.col.f32.f16.f16.f32 "
                 "{%0,%1,%2,%3}, {%4,%5,%6,%7}, {%8,%9}, {%0,%1,%2,%3};"
                 : "+f"(d[0]), "+f"(d[1]), "+f"(d[2]), "+f"(d[3])
                 : "r"(a[0]), "r"(a[1]), "r"(a[2]), "r"(a[3]), "r"(b[0]), "r"(b[1]));
}
__device__ __forceinline__ uint32_t pkh2(__half lo, __half hi) {
    return ((uint32_t)__half_as_ushort(hi) << 16) | __half_as_ushort(lo);
}
// packed fp16x2 tanh (1 MUFU op for two lanes)
__device__ __forceinline__ __half2 tanh_h2(__half2 x) {
    uint32_t xi = *(uint32_t*)&x, ri;
    asm("tanh.approx.f16x2 %0, %1;" : "=r"(ri) : "r"(xi));
    return *(__half2*)&ri;
}
// accurate versions for tail / finale
__device__ __forceinline__ float sigf(float x)   { return 1.0f / (1.0f + __expf(-x)); }
__device__ __forceinline__ float tanh_f(float x) { float e = __expf(2.0f * x); return 1.0f - 2.0f / (e + 1.0f); }

#define BARW(id) asm volatile("bar.sync %0, 256;" :: "r"(id) : "memory")

__global__ __launch_bounds__(NTH, 1)
void lstm_main(const float* __restrict__ x,
               const float* __restrict__ W_num, const float* __restrict__ b_num,
               const float* __restrict__ W_ih,  const float* __restrict__ W_hh,
               const float* __restrict__ b_ih,  const float* __restrict__ b_hh,
               const float* __restrict__ W_aout, const float* __restrict__ b_aout,
               const float* __restrict__ W_fh,   const float* __restrict__ b_fh)
{
    extern __shared__ char smem[];
    const uint32_t sb = smem_u32(smem);

    float*  x_s   = (float*)(smem + X_OFF);
    float*  hf_s  = (float*)(smem + HF_OFF);
    float*  cf_s  = (float*)(smem + CF_OFF);
    float2* vcb_s = (float2*)(smem + VCB_OFF);
    float*  red   = (float*)(smem + RED_OFF);

    const int tid  = threadIdx.x;
    const int l    = tid & 31;
    const int wid  = tid >> 5;
    const int wm   = wid >> 3;          // row-group: rows wm*32 .. +31
    const int wn   = wid & 7;           // unit-group: units wn*8 .. +7
    const int c    = l & 3;
    const int quad = l >> 2;
    const int u0   = 8 * wn + 2 * c;    // this thread's unit pair u0, u0+1
    const int barid = 1 + wm;           // per-row-group named barrier

    // ---- zero h buffer 0 (h(0)=0) ----
    for (int i = tid; i < HB_BUF / 4; i += NTH) ((uint32_t*)(smem + HB_OFF))[i] = 0u;

    // ---- stage x rows (padded stride, bank-spread) ----
    {
        const float* xg = x + (size_t)blockIdx.x * (64 * LT);
        for (int i = tid; i < 64 * LT; i += NTH) x_s[(i >> 7) * XS + (i & 127)] = xg[i];
    }

    // ---- rank-1 input precompute, stored at remapped gate index m ----
    // orig gate g = q*64+u (q: 0=i,1=f,2=g,3=o)
    // m = (q>>1)*128 + (u>>3)*16 + (u&1)*8 + ((u>>1)&3)*2 + (q&1)
    // i/f/o gates pre-halved so sig(x) = 0.5*tanh(x_halved)+0.5
    if (tid < 256) {
        int g = tid;
        const float* wr = W_ih + g * 128;   // (256,128); first 64 cols used
        float v = 0.0f, cb = 0.0f;
        #pragma unroll 8
        for (int j = 0; j < 64; ++j) {
            float ww = wr[j];
            v  = fmaf(ww, W_num[j], v);
            cb = fmaf(ww, b_num[j], cb);
        }
        int q = g >> 6, u = g & 63;
        float sc = (q == 2) ? 1.0f : 0.5f;
        int m = (q >> 1) * 128 + (u >> 3) * 16 + (u & 1) * 8 + ((u >> 1) & 3) * 2 + (q & 1);
        vcb_s[m] = make_float2(v * sc, (cb + b_ih[g] + b_hh[g]) * sc);
    }

    // ---- W fragments (fp16, i/f/o pre-halved) in registers ----
    uint32_t Bh[4][4][2];
    #pragma unroll
    for (int nt = 0; nt < 4; ++nt) {
        int u = 8 * wn + 2 * (quad >> 1) + (nt & 1);
        int q = (nt >> 1) * 2 + (quad & 1);
        float sc = (q == 2) ? 1.0f : 0.5f;
        const float* wr = W_hh + (q * 64 + u) * 64;
        #pragma unroll
        for (int kk = 0; kk < 4; ++kk) {
            int j0 = kk * 16 + 2 * c;
            Bh[nt][kk][0] = pkh2(__float2half(wr[j0] * sc),     __float2half(wr[j0 + 1] * sc));
            Bh[nt][kk][1] = pkh2(__float2half(wr[j0 + 8] * sc), __float2half(wr[j0 + 9] * sc));
        }
    }
    __syncthreads();

    // hoist step-invariant gate constants into registers
    float2 P0[4], P1[4];
    #pragma unroll
    for (int nt = 0; nt < 4; ++nt) {
        int mb = (nt >> 1) * 128 + wn * 16 + (nt & 1) * 8 + 2 * c;
        P0[nt] = vcb_s[mb];
        P1[nt] = vcb_s[mb + 1];
    }

    __half2 cst[2][2];   // [mt][rr] packed over z
    cst[0][0] = __float2half2_rn(0.0f);
    cst[0][1] = __float2half2_rn(0.0f);
    cst[1][0] = __float2half2_rn(0.0f);
    cst[1][1] = __float2half2_rn(0.0f);

    const uint32_t abase = sb + HB_OFF + (wm * 32 + (l & 15)) * HROW + (l >> 4) * 16;
    const __half2 HALF2 = __float2half2_rn(0.5f);

    // ================= recurrence: 128 sequential steps =================
    for (int t = 0; t < LT; ++t) {
        // --- init D with rank-1 x-term + fused bias ---
        float D[2][4][4];
        float xv[2][2];
        #pragma unroll
        for (int mt = 0; mt < 2; ++mt) {
            int ra = wm * 32 + mt * 16 + quad;
            xv[mt][0] = x_s[ra * XS + t];
            xv[mt][1] = x_s[(ra + 8) * XS + t];
        }
        #pragma unroll
        for (int nt = 0; nt < 4; ++nt) {
            float2 p0 = P0[nt], p1 = P1[nt];
            #pragma unroll
            for (int mt = 0; mt < 2; ++mt) {
                D[mt][nt][0] = fmaf(xv[mt][0], p0.x, p0.y);
                D[mt][nt][1] = fmaf(xv[mt][0], p1.x, p1.y);
                D[mt][nt][2] = fmaf(xv[mt][1], p0.x, p0.y);
                D[mt][nt][3] = fmaf(xv[mt][1], p1.x, p1.y);
            }
        }

        // --- D += h @ W^T : fp16 mma ---
        const uint32_t ab = abase + (t & 1) * HB_BUF;
        #pragma unroll
        for (int kk = 0; kk < 4; ++kk) {
            uint32_t Ah0[4], Ah1[4];
            ldmx4(Ah0, ab + kk * 32);
            ldmx4(Ah1, ab + 16 * HROW + kk * 32);
            #pragma unroll
            for (int nt = 0; nt < 4; ++nt) {
                mma16816(D[0][nt], Ah0, Bh[nt][kk]);
                mma16816(D[1][nt], Ah1, Bh[nt][kk]);
            }
        }

        // --- epilogue: packed fp16x2 activations (5 MUFU per 2 cells) ---
        char* hnext = smem + HB_OFF + ((t + 1) & 1) * HB_BUF;
        #pragma unroll
        for (int mt = 0; mt < 2; ++mt)
            #pragma unroll
            for (int rr = 0; rr < 2; ++rr) {
                int row = wm * 32 + mt * 16 + quad + 8 * rr;
                // pack gates across z (z=0 lo, z=1 hi); i/f/o already half-scaled
                __half2 gi2 = __floats2half2_rn(D[mt][0][2 * rr],     D[mt][1][2 * rr]);
                __half2 gf2 = __floats2half2_rn(D[mt][0][2 * rr + 1], D[mt][1][2 * rr + 1]);
                __half2 gg2 = __floats2half2_rn(D[mt][2][2 * rr],     D[mt][3][2 * rr]);
                __half2 go2 = __floats2half2_rn(D[mt][2][2 * rr + 1], D[mt][3][2 * rr + 1]);
                __half2 si2 = __hfma2(tanh_h2(gi2), HALF2, HALF2);
                __half2 sf2 = __hfma2(tanh_h2(gf2), HALF2, HALF2);
                __half2 so2 = __hfma2(tanh_h2(go2), HALF2, HALF2);
                __half2 tg2 = tanh_h2(gg2);
                __half2 cn2 = __hfma2(sf2, cst[mt][rr], __hmul2(si2, tg2));
                cst[mt][rr] = cn2;
                __half2 h2 = __hmul2(so2, tanh_h2(cn2));
                if (t < LT - 1) {
                    *(uint32_t*)(hnext + row * HROW + 2 * u0) = *(uint32_t*)&h2;
                } else {
                    hf_s[row * 66 + u0]     = __low2float(h2);
                    hf_s[row * 66 + u0 + 1] = __high2float(h2);
                    cf_s[row * 66 + u0]     = __low2float(cn2);
                    cf_s[row * 66 + u0 + 1] = __high2float(cn2);
                }
            }
        BARW(barid);
    }
    __syncthreads();   // join row-groups before tail overlays

    // ================= tail =================
    float* wa  = (float*)(smem + WA_OFF);    // [j*66+u]
    float* wf  = (float*)(smem + WF_OFF);
    float* hs2 = (float*)(smem + HS2_OFF);   // h_hat staging [r][66]
    for (int idx = tid; idx < 4096; idx += NTH) {
        int u = idx >> 6, j = idx & 63;
        wa[j * 66 + u] = W_aout[idx];
        wf[j * 66 + u] = W_fh[idx];
    }
    __syncthreads();

    const int tw = wid;            // 16 warps
    const int r0 = tw * 4;         // rows r0..r0+3
    const int tu = 2 * l;          // units tu, tu+1

    // h_hat = h @ W_aout^T + b_aout
    float hh2[2][4];
    {
        float b0 = b_aout[tu], b1 = b_aout[tu + 1];
        #pragma unroll
        for (int rr = 0; rr < 4; ++rr) { hh2[0][rr] = b0; hh2[1][rr] = b1; }
        #pragma unroll 8
        for (int j = 0; j < 64; ++j) {
            float w0 = wa[j * 66 + tu], w1 = wa[j * 66 + tu + 1];
            #pragma unroll
            for (int rr = 0; rr < 4; ++rr) {
                float hj = hf_s[(r0 + rr) * 66 + j];
                hh2[0][rr] = fmaf(hj, w0, hh2[0][rr]);
                hh2[1][rr] = fmaf(hj, w1, hh2[1][rr]);
            }
        }
        #pragma unroll
        for (int rr = 0; rr < 4; ++rr) {
            hs2[(r0 + rr) * 66 + tu]     = hh2[0][rr];
            hs2[(r0 + rr) * 66 + tu + 1] = hh2[1][rr];
        }
    }
    __syncthreads();

    // f = h_hat @ W_fh^T + b_fh ; partial sums
    float fv2[2][4];
    {
        float b0 = b_fh[tu], b1 = b_fh[tu + 1];
        #pragma unroll
        for (int rr = 0; rr < 4; ++rr) { fv2[0][rr] = b0; fv2[1][rr] = b1; }
        #pragma unroll 8
        for (int j = 0; j < 64; ++j) {
            float w0 = wf[j * 66 + tu], w1 = wf[j * 66 + tu + 1];
            #pragma unroll
            for (int rr = 0; rr < 4; ++rr) {
                float hj = hs2[(r0 + rr) * 66 + j];
                fv2[0][rr] = fmaf(hj, w0, fv2[0][rr]);
                fv2[1][rr] = fmaf(hj, w1, fv2[1][rr]);
            }
        }
    }

    float fc0 = 0.0f, fc1 = 0.0f, hs0 = 0.0f, hs1 = 0.0f;
    #pragma unroll
    for (int rr = 0; rr < 4; ++rr) {
        fc0 += sigf(fv2[0][rr]) * cf_s[(r0 + rr) * 66 + tu];
        fc1 += sigf(fv2[1][rr]) * cf_s[(r0 + rr) * 66 + tu + 1];
        hs0 += hh2[0][rr];
        hs1 += hh2[1][rr];
    }
    red[tw * 64 + tu]            = fc0;
    red[tw * 64 + tu + 1]        = fc1;
    red[1024 + tw * 64 + tu]     = hs0;
    red[1024 + tw * 64 + tu + 1] = hs1;
    __syncthreads();

    if (tid < 64) {
        float a = 0.0f, b = 0.0f;
        #pragma unroll
        for (int g = 0; g < 16; ++g) {
            a += red[g * 64 + tid];
            b += red[1024 + g * 64 + tid];
        }
        g_Pfc[blockIdx.x * 64 + tid] = a;
        g_Phs[blockIdx.x * 64 + tid] = b;
    }
}

// ================= finale: parallel reduce + object-cell head (1024 thr) =================
__global__ __launch_bounds__(1024, 1)
void lstm_final(const float* __restrict__ W_iouh, const float* __restrict__ b_iouh,
                const float* __restrict__ W_oout, const float* __restrict__ b_oout,
                float* __restrict__ out)
{
    __shared__ float s_fc[16][64];
    __shared__ float s_hs[16][64];
    __shared__ float hsb[64];
    __shared__ float fcb[64];
    __shared__ float s_g[192][4];
    __shared__ float iouv[192];
    __shared__ float hob[64];
    __shared__ float s_o[64][16];

    const int tid = threadIdx.x;   // 1024
    const int q = tid >> 6, u = tid & 63;

    // phase 1: reduce per-block partials (128 blocks -> 16 -> 1)
    float fc = 0.0f, hs = 0.0f;
    #pragma unroll
    for (int b = q; b < NBLK; b += 16) {
        fc += g_Pfc[b * 64 + u];
        hs += g_Phs[b * 64 + u];
    }
    s_fc[q][u] = fc;
    s_hs[q][u] = hs;
    __syncthreads();
    if (tid < 64) {
        float a = 0.0f, b = 0.0f;
        #pragma unroll
        for (int k = 0; k < 16; ++k) { a += s_fc[k][tid]; b += s_hs[k][tid]; }
        fcb[tid] = a;
        hsb[tid] = b;
    }
    __syncthreads();

    // phase 2: iou = hsb @ W_iouh^T + b_iouh  (192 outputs x 4 K-chunks)
    if (tid < 768) {
        int g = tid >> 2, ch = tid & 3;
        const float* wr = W_iouh + g * 64 + ch * 16;
        const float* hp = hsb + ch * 16;
        float s = 0.0f;
        #pragma unroll
        for (int j = 0; j < 16; ++j) s = fmaf(hp[j], wr[j], s);
        s_g[g][ch] = s;
    }
    __syncthreads();
    if (tid < 192)
        iouv[tid] = s_g[tid][0] + s_g[tid][1] + s_g[tid][2] + s_g[tid][3] + b_iouh[tid];
    __syncthreads();

    // phase 3: object cell
    if (tid < 64) {
        float c_obj = sigf(iouv[tid]) * tanh_f(iouv[128 + tid]) + fcb[tid];
        float h_obj = sigf(iouv[64 + tid]) * tanh_f(c_obj);
        hob[tid] = h_obj;
        out[64 + tid] = c_obj;
    }
    __syncthreads();

    // phase 4: out[0:64] = hob @ W_oout^T + b_oout (64 outputs x 16 K-chunks)
    {
        int uo = tid >> 4, ch = tid & 15;
        const float* wr = W_oout + uo * 64 + ch * 4;
        const float* hp = hob + ch * 4;
        float s = 0.0f;
        #pragma unroll
        for (int j = 0; j < 4; ++j) s = fmaf(hp[j], wr[j], s);
        s_o[uo][ch] = s;
    }
    __syncthreads();
    if (tid < 64) {
        float s = b_oout[tid];
        #pragma unroll
        for (int k = 0; k < 16; ++k) s += s_o[tid][k];
        out[tid] = s;
    }
}

extern "C" void kernel_launch(void* const* d_in, const int* in_sizes, int n_in,
                              void* d_out, int out_size)
{
    const float* x      = (const float*)d_in[0];
    const float* W_num  = (const float*)d_in[1];
    const float* b_num  = (const float*)d_in[2];
    const float* W_ih   = (const float*)d_in[3];
    const float* W_hh   = (const float*)d_in[4];
    const float* b_ih   = (const float*)d_in[5];
    const float* b_hh   = (const float*)d_in[6];
    const float* W_aout = (const float*)d_in[7];
    const float* b_aout = (const float*)d_in[8];
    const float* W_fh   = (const float*)d_in[9];
    const float* b_fh   = (const float*)d_in[10];
    const float* W_iouh = (const float*)d_in[11];
    const float* b_iouh = (const float*)d_in[12];
    const float* W_oout = (const float*)d_in[13];
    const float* b_oout = (const float*)d_in[14];

    (void)in_sizes; (void)n_in; (void)out_size;

    cudaFuncSetAttribute(lstm_main, cudaFuncAttributeMaxDynamicSharedMemorySize, SMEM_BYTES);

    lstm_main<<<NBLK, NTH, SMEM_BYTES>>>(x, W_num, b_num, W_ih, W_hh, b_ih, b_hh,
                                         W_aout, b_aout, W_fh, b_fh);
    lstm_final<<<1, 1024>>>(W_iouh, b_iouh, W_oout, b_oout, (float*)d_out);
}